// round 11
// baseline (speedup 1.0000x reference)
#include <cuda_runtime.h>
#include <cuda_bf16.h>
#include <cstdint>

#define DFEAT 128
#define NMAX  50000
#define NPAD  50176      // 49 * 1024
#define EMAX  600000
#define BM    64
#define LDSK  136        // smem row stride (bf16) -> 272B rows
#define SCANB 49
#define GB    148        // graph-build persistent grid (1 block/SM)
#define GBT   1024       // graph-build threads per block

// scratch (no allocations allowed) ------------------------------------------
__device__ __align__(16) float g_h[NMAX * DFEAT];
__device__ __align__(16) int   g_cin[NPAD];
__device__ __align__(16) int   g_cout[NPAD];
__device__ __align__(16) int   g_off[NPAD + 1];
__device__ __align__(16) int   g_cur[NPAD];
__device__ __align__(16) int   g_srcs[EMAX];
__device__ __align__(16) unsigned long long g_state[SCANB];
__device__ __align__(16) __nv_bfloat16 g_wh[128 * 128];
__device__ __align__(16) __nv_bfloat16 g_wl[128 * 128];
__device__ unsigned g_barcnt = 0;
__device__ volatile unsigned g_bargen = 0;

__device__ __forceinline__ void grid_barrier() {
    __threadfence();
    __syncthreads();
    if (threadIdx.x == 0) {
        unsigned gen = g_bargen;
        if (atomicAdd(&g_barcnt, 1u) == GB - 1u) {
            g_barcnt = 0;
            __threadfence();
            g_bargen = gen + 1;
        } else {
            while (g_bargen == gen) __nanosleep(64);
        }
    }
    __syncthreads();
}

__device__ __forceinline__ void ldsm_x4(uint32_t addr, uint32_t& r0, uint32_t& r1,
                                        uint32_t& r2, uint32_t& r3) {
    asm volatile("ldmatrix.sync.aligned.m8n8.x4.shared.b16 {%0,%1,%2,%3}, [%4];"
                 : "=r"(r0), "=r"(r1), "=r"(r2), "=r"(r3) : "r"(addr));
}

__device__ __forceinline__ void mma_bf16(float c[4], const uint32_t a[4],
                                         uint32_t b0, uint32_t b1) {
    asm volatile("mma.sync.aligned.m16n8k16.row.col.f32.bf16.bf16.f32 "
                 "{%0,%1,%2,%3},{%4,%5,%6,%7},{%8,%9},{%0,%1,%2,%3};"
                 : "+f"(c[0]), "+f"(c[1]), "+f"(c[2]), "+f"(c[3])
                 : "r"(a[0]), "r"(a[1]), "r"(a[2]), "r"(a[3]), "r"(b0), "r"(b1));
}

__device__ __forceinline__ void cp_async16(uint32_t saddr, const void* gptr) {
    asm volatile("cp.async.ca.shared.global [%0], [%1], 16;"
                 :: "r"(saddr), "l"(gptr) : "memory");
}

// ---------------------------------------------------------------------------
// Persistent graph-build @1024 thr/blk: zero+Wsplit | count | scan | fill
__global__ void __launch_bounds__(GBT, 1)
k_graph(const int* __restrict__ ei, const float* __restrict__ W, int E) {
    const int tid = threadIdx.x;
    const int gtid = blockIdx.x * GBT + tid;
    const int gs = GB * GBT;

    // ---- phase 0: zero counters + scan state, split W ----
    for (int i = gtid; i < NPAD; i += gs) { g_cin[i] = 0; g_cout[i] = 0; }
    if (gtid < SCANB) g_state[gtid] = 0ULL;
    for (int i = gtid; i < 128 * 128; i += gs) {
        float w = W[i];
        __nv_bfloat16 h = __float2bfloat16_rn(w);
        g_wh[i] = h;
        g_wl[i] = __float2bfloat16_rn(w - __bfloat162float(h));
    }
    grid_barrier();

    // ---- phase 1: degree count ----
    for (int e = gtid; e < E; e += gs) {
        atomicAdd(&g_cout[ei[e]], 1);
        atomicAdd(&g_cin[ei[E + e]], 1);
    }
    grid_barrier();

    // ---- phase 2: exclusive scan (lookback, blocks 0..SCANB-1, tid<256 active) ----
    {
        __shared__ int woff[8];
        __shared__ int s_prefix;
        const bool active = (blockIdx.x < SCANB) && (tid < 256);
        int4 c = make_int4(0, 0, 0, 0);
        int s = 0, v = 0;
        int base = blockIdx.x * 1024 + tid * 4;
        if (active) {
            c = *(const int4*)&g_cin[base];
            s = c.x + c.y + c.z + c.w;
            v = s;
            int lane = tid & 31;
#pragma unroll
            for (int off = 1; off < 32; off <<= 1) {
                int u = __shfl_up_sync(0xFFFFFFFFu, v, off);
                if (lane >= off) v += u;
            }
            if (lane == 31) woff[tid >> 5] = v;
        }
        __syncthreads();
        if (blockIdx.x < SCANB && tid == 0) {
            int blk = blockIdx.x;
            int run = 0;
#pragma unroll
            for (int i = 0; i < 8; i++) { int x = woff[i]; woff[i] = run; run += x; }
            if (blk == 0) {
                atomicExch(&g_state[0], (2ULL << 32) | (unsigned)run);
                s_prefix = 0;
            } else {
                atomicExch(&g_state[blk], (1ULL << 32) | (unsigned)run);
                int exc = 0;
                int p = blk - 1;
                while (p >= 0) {
                    unsigned long long st = atomicAdd(&g_state[p], 0ULL);
                    unsigned flag = (unsigned)(st >> 32);
                    if (flag == 2u) { exc += (int)(st & 0xFFFFFFFFu); break; }
                    if (flag == 1u) { exc += (int)(st & 0xFFFFFFFFu); p--; }
                }
                atomicExch(&g_state[blk], (2ULL << 32) | (unsigned)(exc + run));
                s_prefix = exc;
            }
        }
        __syncthreads();
        if (active) {
            int run = (v - s) + woff[tid >> 5] + s_prefix;
            g_off[base]     = run; g_cur[base]     = run; run += c.x;
            g_off[base + 1] = run; g_cur[base + 1] = run; run += c.y;
            g_off[base + 2] = run; g_cur[base + 2] = run; run += c.z;
            g_off[base + 3] = run; g_cur[base + 3] = run;
        }
        if (blockIdx.x == 0 && tid == 0) g_off[NPAD] = E;
    }
    grid_barrier();

    // ---- phase 3: CSR fill ----
    for (int e = gtid; e < E; e += gs) {
        int s = ei[e], d = ei[E + e];
        int slot = atomicAdd(&g_cur[d], 1);
        g_srcs[slot] = s;
    }
}

// ---------------------------------------------------------------------------
// Persistent fused logmap0 + GEMM + bias + dinv[row] scale.
// 3-term bf16 split (hh + hl + lh; ll dropped, ~2^-18 relative).
__global__ void __launch_bounds__(256, 2)
k_logmap_gemm(const float* __restrict__ x, const float* __restrict__ b,
              int N, int ntiles) {
    extern __shared__ __align__(16) char smraw[];
    __nv_bfloat16* swh = (__nv_bfloat16*)smraw;          // [128][LDSK]
    __nv_bfloat16* swl = swh + 128 * LDSK;
    __nv_bfloat16* sxh = swl + 128 * LDSK;               // [BM][LDSK]
    __nv_bfloat16* sxl = sxh + BM * LDSK;

    const int tid  = threadIdx.x;
    const int warp = tid >> 5, lane = tid & 31;

    for (int c = tid; c < 2048; c += 256) {
        int row = c >> 4, col8 = (c & 15) * 8;
        uint32_t sh = (uint32_t)__cvta_generic_to_shared(&swh[row * LDSK + col8]);
        cp_async16(sh, &g_wh[row * 128 + col8]);
        uint32_t sl = (uint32_t)__cvta_generic_to_shared(&swl[row * LDSK + col8]);
        cp_async16(sl, &g_wl[row * 128 + col8]);
    }
    asm volatile("cp.async.commit_group;");

    const int wm = warp & 3, wn = warp >> 2;
    const int m0 = wm * 16, n0b = wn * 64;
    const int mat = lane >> 3, mr = lane & 7;
    const int arow = m0 + mr + 8 * (mat & 1);
    const int aoff = 8 * (mat >> 1);
    uint32_t aBaseH = (uint32_t)__cvta_generic_to_shared(&sxh[arow * LDSK + aoff]);
    uint32_t aBaseL = (uint32_t)__cvta_generic_to_shared(&sxl[arow * LDSK + aoff]);
    uint32_t bBaseH[4], bBaseL[4];
#pragma unroll
    for (int g = 0; g < 4; g++) {
        int nrow = n0b + g * 16 + mr + 8 * (mat >> 1);
        int koff = 8 * (mat & 1);
        bBaseH[g] = (uint32_t)__cvta_generic_to_shared(&swh[nrow * LDSK + koff]);
        bBaseL[g] = (uint32_t)__cvta_generic_to_shared(&swl[nrow * LDSK + koff]);
    }

    bool wwait = true;
    const float4* x4 = (const float4*)x;

    for (int tile = blockIdx.x; tile < ntiles; tile += gridDim.x) {
        const int row0 = tile * BM;

#pragma unroll
        for (int rr = 0; rr < 8; rr++) {
            int r = warp * 8 + rr;
            int row = row0 + r;
            float4 v = (row < N) ? x4[row * 32 + lane] : make_float4(0.f, 0.f, 0.f, 0.f);
            float s = v.x * v.x + v.y * v.y + v.z * v.z + v.w * v.w;
#pragma unroll
            for (int off = 16; off; off >>= 1) s += __shfl_xor_sync(0xFFFFFFFFu, s, off);
            float norm = sqrtf(s);
            float nc = fminf(fmaxf(norm, 1e-15f), 1.0f - 1e-5f);
            float scale = atanhf(nc) / fmaxf(norm, 1e-15f);
            v.x *= scale; v.y *= scale; v.z *= scale; v.w *= scale;
            __nv_bfloat16 h0 = __float2bfloat16_rn(v.x), h1 = __float2bfloat16_rn(v.y);
            __nv_bfloat16 h2 = __float2bfloat16_rn(v.z), h3 = __float2bfloat16_rn(v.w);
            __nv_bfloat16 l0 = __float2bfloat16_rn(v.x - __bfloat162float(h0));
            __nv_bfloat16 l1 = __float2bfloat16_rn(v.y - __bfloat162float(h1));
            __nv_bfloat16 l2 = __float2bfloat16_rn(v.z - __bfloat162float(h2));
            __nv_bfloat16 l3 = __float2bfloat16_rn(v.w - __bfloat162float(h3));
            int kc = lane * 4;
            __nv_bfloat162 hh0; hh0.x = h0; hh0.y = h1;
            __nv_bfloat162 hh1; hh1.x = h2; hh1.y = h3;
            __nv_bfloat162 ll0; ll0.x = l0; ll0.y = l1;
            __nv_bfloat162 ll1; ll1.x = l2; ll1.y = l3;
            *(__nv_bfloat162*)&sxh[r * LDSK + kc]     = hh0;
            *(__nv_bfloat162*)&sxh[r * LDSK + kc + 2] = hh1;
            *(__nv_bfloat162*)&sxl[r * LDSK + kc]     = ll0;
            *(__nv_bfloat162*)&sxl[r * LDSK + kc + 2] = ll1;
        }
        if (wwait) {
            asm volatile("cp.async.wait_group 0;");
            wwait = false;
        }
        __syncthreads();

        float acc[8][4];
#pragma unroll
        for (int f = 0; f < 8; f++)
#pragma unroll
            for (int j = 0; j < 4; j++) acc[f][j] = 0.f;

        uint32_t ah[2][4], al[2][4];
        uint32_t bh[2][4], bl[2][4];

        ldsm_x4(aBaseH, ah[0][0], ah[0][1], ah[0][2], ah[0][3]);
        ldsm_x4(aBaseL, al[0][0], al[0][1], al[0][2], al[0][3]);

#pragma unroll
        for (int kk = 0; kk < 8; kk++) {
            const uint32_t kb = kk * 32;
            const int cur = kk & 1, nxt = cur ^ 1;
            ldsm_x4(bBaseH[0] + kb, bh[0][0], bh[0][1], bh[0][2], bh[0][3]);
            ldsm_x4(bBaseL[0] + kb, bl[0][0], bl[0][1], bl[0][2], bl[0][3]);
            if (kk < 7) {
                ldsm_x4(aBaseH + kb + 32, ah[nxt][0], ah[nxt][1], ah[nxt][2], ah[nxt][3]);
                ldsm_x4(aBaseL + kb + 32, al[nxt][0], al[nxt][1], al[nxt][2], al[nxt][3]);
            }
#pragma unroll
            for (int g = 0; g < 4; g++) {
                const int gb = g & 1, gn = gb ^ 1;
                if (g < 3) {
                    ldsm_x4(bBaseH[g + 1] + kb, bh[gn][0], bh[gn][1], bh[gn][2], bh[gn][3]);
                    ldsm_x4(bBaseL[g + 1] + kb, bl[gn][0], bl[gn][1], bl[gn][2], bl[gn][3]);
                }
#pragma unroll
                for (int o = 0; o < 2; o++) {
                    const int f = 2 * g + o;
                    uint32_t b0h = bh[gb][2 * o], b1h = bh[gb][2 * o + 1];
                    uint32_t b0l = bl[gb][2 * o], b1l = bl[gb][2 * o + 1];
                    mma_bf16(acc[f], ah[cur], b0h, b1h);   // hh
                    mma_bf16(acc[f], ah[cur], b0l, b1l);   // hl
                    mma_bf16(acc[f], al[cur], b0h, b1h);   // lh  (ll dropped)
                }
            }
        }
        __syncthreads();

        int r0r = row0 + m0 + (lane >> 2);
        int r1r = r0r + 8;
        float di0 = 0.f, di1 = 0.f;
        if (r0r < N) di0 = rsqrtf(fmaxf((float)(g_cin[r0r] + g_cout[r0r]), 1.0f));
        if (r1r < N) di1 = rsqrtf(fmaxf((float)(g_cin[r1r] + g_cout[r1r]), 1.0f));
        float2* h2p = (float2*)g_h;
#pragma unroll
        for (int f = 0; f < 8; f++) {
            int c = n0b + f * 8 + 2 * (lane & 3);
            float bx = b[c], by = b[c + 1];
            if (r0r < N) {
                float2 o0;
                o0.x = (acc[f][0] + bx) * di0;
                o0.y = (acc[f][1] + by) * di0;
                h2p[(r0r * DFEAT + c) >> 1] = o0;
            }
            if (r1r < N) {
                float2 o1;
                o1.x = (acc[f][2] + bx) * di1;
                o1.y = (acc[f][3] + by) * di1;
                h2p[(r1r * DFEAT + c) >> 1] = o1;
            }
        }
    }
}

// ---------------------------------------------------------------------------
// CSR gather-sum + dinv[dst] + expmap0, one warp per node. No atomics.
__global__ void k_gather(float* __restrict__ out, int N) {
    int gw = (blockIdx.x * blockDim.x + threadIdx.x) >> 5;
    int lane = threadIdx.x & 31;
    if (gw >= N) return;
    int beg = g_off[gw], end = g_off[gw + 1];
    const float4* h4 = (const float4*)g_h;

    float4 a0 = make_float4(0.f, 0.f, 0.f, 0.f);
    float4 a1 = make_float4(0.f, 0.f, 0.f, 0.f);
    int p = beg;
    for (; p + 2 <= end; p += 2) {
        int s0 = __ldg(&g_srcs[p]);
        int s1 = __ldg(&g_srcs[p + 1]);
        float4 v0 = h4[s0 * 32 + lane];
        float4 v1 = h4[s1 * 32 + lane];
        a0.x += v0.x; a0.y += v0.y; a0.z += v0.z; a0.w += v0.w;
        a1.x += v1.x; a1.y += v1.y; a1.z += v1.z; a1.w += v1.w;
    }
    if (p < end) {
        int s0 = __ldg(&g_srcs[p]);
        float4 v0 = h4[s0 * 32 + lane];
        a0.x += v0.x; a0.y += v0.y; a0.z += v0.z; a0.w += v0.w;
    }
    float di = rsqrtf(fmaxf((float)(g_cin[gw] + g_cout[gw]), 1.0f));
    float4 acc;
    acc.x = (a0.x + a1.x) * di;
    acc.y = (a0.y + a1.y) * di;
    acc.z = (a0.z + a1.z) * di;
    acc.w = (a0.w + a1.w) * di;

    float s = acc.x * acc.x + acc.y * acc.y + acc.z * acc.z + acc.w * acc.w;
#pragma unroll
    for (int off = 16; off; off >>= 1) s += __shfl_xor_sync(0xFFFFFFFFu, s, off);
    float norm = sqrtf(s);
    float scale = tanhf(norm) / fmaxf(norm, 1e-15f);
    acc.x *= scale; acc.y *= scale; acc.z *= scale; acc.w *= scale;
    ((float4*)out)[gw * 32 + lane] = acc;
}

// ---------------------------------------------------------------------------
extern "C" void kernel_launch(void* const* d_in, const int* in_sizes, int n_in,
                              void* d_out, int out_size) {
    const float* x  = (const float*)d_in[0];
    const int*   ei = (const int*)d_in[1];
    const float* W  = (const float*)d_in[2];
    const float* b  = (const float*)d_in[3];
    float* out = (float*)d_out;

    const int N = in_sizes[0] / DFEAT;
    const int E = in_sizes[1] / 2;

    // 1. persistent graph build (zero, count, scan, fill) — one launch, 32 warps/SM
    k_graph<<<GB, GBT>>>(ei, W, E);
    // 2. persistent logmap+GEMM
    {
        const int SMEM = (2 * 128 * LDSK + 2 * BM * LDSK) * (int)sizeof(__nv_bfloat16);
        cudaFuncSetAttribute(k_logmap_gemm,
                             cudaFuncAttributeMaxDynamicSharedMemorySize, SMEM);
        const int ntiles = (N + BM - 1) / BM;
        int grid = 296;
        if (grid > ntiles) grid = ntiles;
        k_logmap_gemm<<<grid, 256, SMEM>>>(x, b, N, ntiles);
    }
    // 3. CSR gather + expmap
    {
        long long threads = (long long)N * 32;
        int grid = (int)((threads + 255) / 256);
        k_gather<<<grid, 256>>>(out, N);
    }
}

// round 12
// speedup vs baseline: 1.0247x; 1.0247x over previous
#include <cuda_runtime.h>
#include <cuda_bf16.h>
#include <cstdint>

#define DFEAT 128
#define NMAX  50000
#define NPAD  50176      // 49 * 1024
#define EMAX  600000
#define BM    64
#define LDSK  136        // smem row stride (bf16) -> 272B rows
#define SCANB 49

// scratch (no allocations allowed). All zero-initialized at module load;
// k_gather's epilogue restores the zeros each run (deterministic, graph-safe).
__device__ __align__(16) float g_h[NMAX * DFEAT];
__device__ __align__(16) int   g_cin[NPAD];
__device__ __align__(16) int   g_cout[NPAD];
__device__ __align__(16) int   g_off[NPAD + 1];
__device__ __align__(16) int   g_cur[NPAD];
__device__ __align__(16) int   g_srcs[EMAX];
__device__ __align__(16) unsigned long long g_state[SCANB];
__device__ __align__(16) __nv_bfloat16 g_wh[128 * 128];
__device__ __align__(16) __nv_bfloat16 g_wl[128 * 128];

__device__ __forceinline__ void ldsm_x4(uint32_t addr, uint32_t& r0, uint32_t& r1,
                                        uint32_t& r2, uint32_t& r3) {
    asm volatile("ldmatrix.sync.aligned.m8n8.x4.shared.b16 {%0,%1,%2,%3}, [%4];"
                 : "=r"(r0), "=r"(r1), "=r"(r2), "=r"(r3) : "r"(addr));
}

__device__ __forceinline__ void mma_bf16(float c[4], const uint32_t a[4],
                                         uint32_t b0, uint32_t b1) {
    asm volatile("mma.sync.aligned.m16n8k16.row.col.f32.bf16.bf16.f32 "
                 "{%0,%1,%2,%3},{%4,%5,%6,%7},{%8,%9},{%0,%1,%2,%3};"
                 : "+f"(c[0]), "+f"(c[1]), "+f"(c[2]), "+f"(c[3])
                 : "r"(a[0]), "r"(a[1]), "r"(a[2]), "r"(a[3]), "r"(b0), "r"(b1));
}

__device__ __forceinline__ void cp_async16(uint32_t saddr, const void* gptr) {
    asm volatile("cp.async.ca.shared.global [%0], [%1], 16;"
                 :: "r"(saddr), "l"(gptr) : "memory");
}

// ---------------------------------------------------------------------------
// degree count (counters pre-zeroed by previous run's gather) + W bf16 split
__global__ void k_count(const int* __restrict__ ei, const float* __restrict__ W, int E) {
    int e = blockIdx.x * blockDim.x + threadIdx.x;
    if (e < 128 * 128) {
        float w = W[e];
        __nv_bfloat16 h = __float2bfloat16_rn(w);
        g_wh[e] = h;
        g_wl[e] = __float2bfloat16_rn(w - __bfloat162float(h));
    }
    if (e >= E) return;
    atomicAdd(&g_cout[ei[e]], 1);        // src out-degree
    atomicAdd(&g_cin[ei[E + e]], 1);     // dst in-degree (= CSR count)
}

// ---------------------------------------------------------------------------
// Single-pass exclusive scan of g_cin -> g_off/g_cur (decoupled lookback).
// 49 blocks x 256 thr, 4 elems/thr; all co-resident. g_state pre-zeroed.
__global__ void k_scan(int E) {
    __shared__ int woff[8];
    __shared__ int s_prefix;
    int blk = blockIdx.x, t = threadIdx.x;
    int lane = t & 31, w = t >> 5;
    int base = blk * 1024 + t * 4;
    int4 c = *(const int4*)&g_cin[base];
    int s = c.x + c.y + c.z + c.w;
    int v = s;
#pragma unroll
    for (int off = 1; off < 32; off <<= 1) {
        int u = __shfl_up_sync(0xFFFFFFFFu, v, off);
        if (lane >= off) v += u;
    }
    if (lane == 31) woff[w] = v;
    __syncthreads();
    if (t == 0) {
        int run = 0;
#pragma unroll
        for (int i = 0; i < 8; i++) { int x = woff[i]; woff[i] = run; run += x; }
        if (blk == 0) {
            atomicExch(&g_state[0], (2ULL << 32) | (unsigned)run);
            s_prefix = 0;
        } else {
            atomicExch(&g_state[blk], (1ULL << 32) | (unsigned)run);
            int exc = 0;
            int p = blk - 1;
            while (p >= 0) {
                unsigned long long st = atomicAdd(&g_state[p], 0ULL);
                unsigned flag = (unsigned)(st >> 32);
                if (flag == 2u) { exc += (int)(st & 0xFFFFFFFFu); break; }
                if (flag == 1u) { exc += (int)(st & 0xFFFFFFFFu); p--; }
            }
            atomicExch(&g_state[blk], (2ULL << 32) | (unsigned)(exc + run));
            s_prefix = exc;
        }
    }
    __syncthreads();
    int run = (v - s) + woff[w] + s_prefix;
    g_off[base]     = run; g_cur[base]     = run; run += c.x;
    g_off[base + 1] = run; g_cur[base + 1] = run; run += c.y;
    g_off[base + 2] = run; g_cur[base + 2] = run; run += c.z;
    g_off[base + 3] = run; g_cur[base + 3] = run;
    if (blk == 0 && t == 0) g_off[NPAD] = E;
}

__global__ void k_fill(const int* __restrict__ ei, int E) {
    int e = blockIdx.x * blockDim.x + threadIdx.x;
    if (e >= E) return;
    int s = ei[e], d = ei[E + e];
    int slot = atomicAdd(&g_cur[d], 1);
    g_srcs[slot] = s;
}

// ---------------------------------------------------------------------------
// Persistent fused logmap0 + GEMM + bias + dinv[row] scale.
// 3-term bf16 split (hh + hl + lh; ll term ~2^-18 relative, dropped).
__global__ void __launch_bounds__(256, 2)
k_logmap_gemm(const float* __restrict__ x, const float* __restrict__ b,
              int N, int ntiles) {
    extern __shared__ __align__(16) char smraw[];
    __nv_bfloat16* swh = (__nv_bfloat16*)smraw;          // [128][LDSK]
    __nv_bfloat16* swl = swh + 128 * LDSK;
    __nv_bfloat16* sxh = swl + 128 * LDSK;               // [BM][LDSK]
    __nv_bfloat16* sxl = sxh + BM * LDSK;

    const int tid  = threadIdx.x;
    const int warp = tid >> 5, lane = tid & 31;

    for (int c = tid; c < 2048; c += 256) {
        int row = c >> 4, col8 = (c & 15) * 8;
        uint32_t sh = (uint32_t)__cvta_generic_to_shared(&swh[row * LDSK + col8]);
        cp_async16(sh, &g_wh[row * 128 + col8]);
        uint32_t sl = (uint32_t)__cvta_generic_to_shared(&swl[row * LDSK + col8]);
        cp_async16(sl, &g_wl[row * 128 + col8]);
    }
    asm volatile("cp.async.commit_group;");

    const int wm = warp & 3, wn = warp >> 2;
    const int m0 = wm * 16, n0b = wn * 64;
    const int mat = lane >> 3, mr = lane & 7;
    const int arow = m0 + mr + 8 * (mat & 1);
    const int aoff = 8 * (mat >> 1);
    uint32_t aBaseH = (uint32_t)__cvta_generic_to_shared(&sxh[arow * LDSK + aoff]);
    uint32_t aBaseL = (uint32_t)__cvta_generic_to_shared(&sxl[arow * LDSK + aoff]);
    uint32_t bBaseH[4], bBaseL[4];
#pragma unroll
    for (int g = 0; g < 4; g++) {
        int nrow = n0b + g * 16 + mr + 8 * (mat >> 1);
        int koff = 8 * (mat & 1);
        bBaseH[g] = (uint32_t)__cvta_generic_to_shared(&swh[nrow * LDSK + koff]);
        bBaseL[g] = (uint32_t)__cvta_generic_to_shared(&swl[nrow * LDSK + koff]);
    }

    bool wwait = true;
    const float4* x4 = (const float4*)x;

    for (int tile = blockIdx.x; tile < ntiles; tile += gridDim.x) {
        const int row0 = tile * BM;

#pragma unroll
        for (int rr = 0; rr < 8; rr++) {
            int r = warp * 8 + rr;
            int row = row0 + r;
            float4 v = (row < N) ? x4[row * 32 + lane] : make_float4(0.f, 0.f, 0.f, 0.f);
            float s = v.x * v.x + v.y * v.y + v.z * v.z + v.w * v.w;
#pragma unroll
            for (int off = 16; off; off >>= 1) s += __shfl_xor_sync(0xFFFFFFFFu, s, off);
            float norm = sqrtf(s);
            float nc = fminf(fmaxf(norm, 1e-15f), 1.0f - 1e-5f);
            float scale = atanhf(nc) / fmaxf(norm, 1e-15f);
            v.x *= scale; v.y *= scale; v.z *= scale; v.w *= scale;
            __nv_bfloat16 h0 = __float2bfloat16_rn(v.x), h1 = __float2bfloat16_rn(v.y);
            __nv_bfloat16 h2 = __float2bfloat16_rn(v.z), h3 = __float2bfloat16_rn(v.w);
            __nv_bfloat16 l0 = __float2bfloat16_rn(v.x - __bfloat162float(h0));
            __nv_bfloat16 l1 = __float2bfloat16_rn(v.y - __bfloat162float(h1));
            __nv_bfloat16 l2 = __float2bfloat16_rn(v.z - __bfloat162float(h2));
            __nv_bfloat16 l3 = __float2bfloat16_rn(v.w - __bfloat162float(h3));
            int kc = lane * 4;
            __nv_bfloat162 hh0; hh0.x = h0; hh0.y = h1;
            __nv_bfloat162 hh1; hh1.x = h2; hh1.y = h3;
            __nv_bfloat162 ll0; ll0.x = l0; ll0.y = l1;
            __nv_bfloat162 ll1; ll1.x = l2; ll1.y = l3;
            *(__nv_bfloat162*)&sxh[r * LDSK + kc]     = hh0;
            *(__nv_bfloat162*)&sxh[r * LDSK + kc + 2] = hh1;
            *(__nv_bfloat162*)&sxl[r * LDSK + kc]     = ll0;
            *(__nv_bfloat162*)&sxl[r * LDSK + kc + 2] = ll1;
        }
        if (wwait) {
            asm volatile("cp.async.wait_group 0;");
            wwait = false;
        }
        __syncthreads();

        float acc[8][4];
#pragma unroll
        for (int f = 0; f < 8; f++)
#pragma unroll
            for (int j = 0; j < 4; j++) acc[f][j] = 0.f;

        uint32_t ah[2][4], al[2][4];
        uint32_t bh[2][4], bl[2][4];

        ldsm_x4(aBaseH, ah[0][0], ah[0][1], ah[0][2], ah[0][3]);
        ldsm_x4(aBaseL, al[0][0], al[0][1], al[0][2], al[0][3]);

#pragma unroll
        for (int kk = 0; kk < 8; kk++) {
            const uint32_t kb = kk * 32;
            const int cur = kk & 1, nxt = cur ^ 1;
            ldsm_x4(bBaseH[0] + kb, bh[0][0], bh[0][1], bh[0][2], bh[0][3]);
            ldsm_x4(bBaseL[0] + kb, bl[0][0], bl[0][1], bl[0][2], bl[0][3]);
            if (kk < 7) {
                ldsm_x4(aBaseH + kb + 32, ah[nxt][0], ah[nxt][1], ah[nxt][2], ah[nxt][3]);
                ldsm_x4(aBaseL + kb + 32, al[nxt][0], al[nxt][1], al[nxt][2], al[nxt][3]);
            }
#pragma unroll
            for (int g = 0; g < 4; g++) {
                const int gb = g & 1, gn = gb ^ 1;
                if (g < 3) {
                    ldsm_x4(bBaseH[g + 1] + kb, bh[gn][0], bh[gn][1], bh[gn][2], bh[gn][3]);
                    ldsm_x4(bBaseL[g + 1] + kb, bl[gn][0], bl[gn][1], bl[gn][2], bl[gn][3]);
                }
#pragma unroll
                for (int o = 0; o < 2; o++) {
                    const int f = 2 * g + o;
                    uint32_t b0h = bh[gb][2 * o], b1h = bh[gb][2 * o + 1];
                    uint32_t b0l = bl[gb][2 * o], b1l = bl[gb][2 * o + 1];
                    mma_bf16(acc[f], ah[cur], b0h, b1h);   // hh
                    mma_bf16(acc[f], ah[cur], b0l, b1l);   // hl
                    mma_bf16(acc[f], al[cur], b0h, b1h);   // lh (ll dropped)
                }
            }
        }
        __syncthreads();

        int r0r = row0 + m0 + (lane >> 2);
        int r1r = r0r + 8;
        float di0 = 0.f, di1 = 0.f;
        if (r0r < N) di0 = rsqrtf(fmaxf((float)(g_cin[r0r] + g_cout[r0r]), 1.0f));
        if (r1r < N) di1 = rsqrtf(fmaxf((float)(g_cin[r1r] + g_cout[r1r]), 1.0f));
        float2* h2p = (float2*)g_h;
#pragma unroll
        for (int f = 0; f < 8; f++) {
            int c = n0b + f * 8 + 2 * (lane & 3);
            float bx = b[c], by = b[c + 1];
            if (r0r < N) {
                float2 o0;
                o0.x = (acc[f][0] + bx) * di0;
                o0.y = (acc[f][1] + by) * di0;
                h2p[(r0r * DFEAT + c) >> 1] = o0;
            }
            if (r1r < N) {
                float2 o1;
                o1.x = (acc[f][2] + bx) * di1;
                o1.y = (acc[f][3] + by) * di1;
                h2p[(r1r * DFEAT + c) >> 1] = o1;
            }
        }
    }
}

// ---------------------------------------------------------------------------
// CSR gather-sum + dinv[dst] + expmap0. Epilogue restores zeroed counters
// and scan state for the next invocation (graph-replay safe).
__global__ void k_gather(float* __restrict__ out, int N) {
    int t = blockIdx.x * blockDim.x + threadIdx.x;
    if (t < SCANB) g_state[t] = 0ULL;
    int gw = t >> 5;
    int lane = threadIdx.x & 31;
    if (gw >= N) return;
    int beg = g_off[gw], end = g_off[gw + 1];
    const float4* h4 = (const float4*)g_h;

    float4 a0 = make_float4(0.f, 0.f, 0.f, 0.f);
    float4 a1 = make_float4(0.f, 0.f, 0.f, 0.f);
    int p = beg;
    for (; p + 2 <= end; p += 2) {
        int s0 = __ldg(&g_srcs[p]);
        int s1 = __ldg(&g_srcs[p + 1]);
        float4 v0 = h4[s0 * 32 + lane];
        float4 v1 = h4[s1 * 32 + lane];
        a0.x += v0.x; a0.y += v0.y; a0.z += v0.z; a0.w += v0.w;
        a1.x += v1.x; a1.y += v1.y; a1.z += v1.z; a1.w += v1.w;
    }
    if (p < end) {
        int s0 = __ldg(&g_srcs[p]);
        float4 v0 = h4[s0 * 32 + lane];
        a0.x += v0.x; a0.y += v0.y; a0.z += v0.z; a0.w += v0.w;
    }
    float di = rsqrtf(fmaxf((float)(g_cin[gw] + g_cout[gw]), 1.0f));
    // reset counters for next run (after the read above)
    if (lane == 0) { g_cin[gw] = 0; g_cout[gw] = 0; }
    float4 acc;
    acc.x = (a0.x + a1.x) * di;
    acc.y = (a0.y + a1.y) * di;
    acc.z = (a0.z + a1.z) * di;
    acc.w = (a0.w + a1.w) * di;

    float s = acc.x * acc.x + acc.y * acc.y + acc.z * acc.z + acc.w * acc.w;
#pragma unroll
    for (int off = 16; off; off >>= 1) s += __shfl_xor_sync(0xFFFFFFFFu, s, off);
    float norm = sqrtf(s);
    float scale = tanhf(norm) / fmaxf(norm, 1e-15f);
    acc.x *= scale; acc.y *= scale; acc.z *= scale; acc.w *= scale;
    ((float4*)out)[gw * 32 + lane] = acc;
}

// ---------------------------------------------------------------------------
extern "C" void kernel_launch(void* const* d_in, const int* in_sizes, int n_in,
                              void* d_out, int out_size) {
    const float* x  = (const float*)d_in[0];
    const int*   ei = (const int*)d_in[1];
    const float* W  = (const float*)d_in[2];
    const float* b  = (const float*)d_in[3];
    float* out = (float*)d_out;

    const int N = in_sizes[0] / DFEAT;
    const int E = in_sizes[1] / 2;

    k_count<<<(E + 255) / 256, 256>>>(ei, W, E);
    k_scan<<<SCANB, 256>>>(E);
    k_fill<<<(E + 255) / 256, 256>>>(ei, E);
    {
        const int SMEM = (2 * 128 * LDSK + 2 * BM * LDSK) * (int)sizeof(__nv_bfloat16);
        cudaFuncSetAttribute(k_logmap_gemm,
                             cudaFuncAttributeMaxDynamicSharedMemorySize, SMEM);
        const int ntiles = (N + BM - 1) / BM;
        int grid = 296;
        if (grid > ntiles) grid = ntiles;
        k_logmap_gemm<<<grid, 256, SMEM>>>(x, b, N, ntiles);
    }
    {
        long long threads = (long long)N * 32;
        int grid = (int)((threads + 255) / 256);
        k_gather<<<grid, 256>>>(out, N);
    }
}

// round 13
// speedup vs baseline: 1.2311x; 1.2014x over previous
#include <cuda_runtime.h>
#include <cuda_bf16.h>
#include <cuda_fp16.h>
#include <cstdint>

#define DFEAT 128
#define NMAX  50000
#define NPAD  50176      // 49 * 1024
#define EMAX  600000
#define BM    64
#define LDSK  136        // smem row stride (bf16) -> 272B rows
#define SCANB 49

// scratch (no allocations allowed). Zero-initialized at load; k_gather's
// epilogue restores zeros each run (deterministic, graph-safe).
__device__ __align__(16) __half g_h[NMAX * DFEAT];    // fp16 features (12.8 MB)
__device__ __align__(16) int   g_cin[NPAD];
__device__ __align__(16) int   g_cout[NPAD];
__device__ __align__(16) int   g_off[NPAD + 1];
__device__ __align__(16) int   g_cur[NPAD];
__device__ __align__(16) int   g_srcs[EMAX];
__device__ __align__(16) unsigned long long g_state[SCANB];
__device__ __align__(16) __nv_bfloat16 g_wh[128 * 128];
__device__ __align__(16) __nv_bfloat16 g_wl[128 * 128];

__device__ __forceinline__ void ldsm_x4(uint32_t addr, uint32_t& r0, uint32_t& r1,
                                        uint32_t& r2, uint32_t& r3) {
    asm volatile("ldmatrix.sync.aligned.m8n8.x4.shared.b16 {%0,%1,%2,%3}, [%4];"
                 : "=r"(r0), "=r"(r1), "=r"(r2), "=r"(r3) : "r"(addr));
}

__device__ __forceinline__ void mma_bf16(float c[4], const uint32_t a[4],
                                         uint32_t b0, uint32_t b1) {
    asm volatile("mma.sync.aligned.m16n8k16.row.col.f32.bf16.bf16.f32 "
                 "{%0,%1,%2,%3},{%4,%5,%6,%7},{%8,%9},{%0,%1,%2,%3};"
                 : "+f"(c[0]), "+f"(c[1]), "+f"(c[2]), "+f"(c[3])
                 : "r"(a[0]), "r"(a[1]), "r"(a[2]), "r"(a[3]), "r"(b0), "r"(b1));
}

__device__ __forceinline__ void cp_async16(uint32_t saddr, const void* gptr) {
    asm volatile("cp.async.ca.shared.global [%0], [%1], 16;"
                 :: "r"(saddr), "l"(gptr) : "memory");
}

// ---------------------------------------------------------------------------
// degree count (counters pre-zeroed by previous run's gather) + W bf16 split
__global__ void k_count(const int* __restrict__ ei, const float* __restrict__ W, int E) {
    int e = blockIdx.x * blockDim.x + threadIdx.x;
    if (e < 128 * 128) {
        float w = W[e];
        __nv_bfloat16 h = __float2bfloat16_rn(w);
        g_wh[e] = h;
        g_wl[e] = __float2bfloat16_rn(w - __bfloat162float(h));
    }
    if (e >= E) return;
    atomicAdd(&g_cout[ei[e]], 1);        // src out-degree
    atomicAdd(&g_cin[ei[E + e]], 1);     // dst in-degree (= CSR count)
}

// ---------------------------------------------------------------------------
// Single-pass exclusive scan (decoupled lookback). 49 co-resident blocks.
__global__ void k_scan(int E) {
    __shared__ int woff[8];
    __shared__ int s_prefix;
    int blk = blockIdx.x, t = threadIdx.x;
    int lane = t & 31, w = t >> 5;
    int base = blk * 1024 + t * 4;
    int4 c = *(const int4*)&g_cin[base];
    int s = c.x + c.y + c.z + c.w;
    int v = s;
#pragma unroll
    for (int off = 1; off < 32; off <<= 1) {
        int u = __shfl_up_sync(0xFFFFFFFFu, v, off);
        if (lane >= off) v += u;
    }
    if (lane == 31) woff[w] = v;
    __syncthreads();
    if (t == 0) {
        int run = 0;
#pragma unroll
        for (int i = 0; i < 8; i++) { int x = woff[i]; woff[i] = run; run += x; }
        if (blk == 0) {
            atomicExch(&g_state[0], (2ULL << 32) | (unsigned)run);
            s_prefix = 0;
        } else {
            atomicExch(&g_state[blk], (1ULL << 32) | (unsigned)run);
            int exc = 0;
            int p = blk - 1;
            while (p >= 0) {
                unsigned long long st = atomicAdd(&g_state[p], 0ULL);
                unsigned flag = (unsigned)(st >> 32);
                if (flag == 2u) { exc += (int)(st & 0xFFFFFFFFu); break; }
                if (flag == 1u) { exc += (int)(st & 0xFFFFFFFFu); p--; }
            }
            atomicExch(&g_state[blk], (2ULL << 32) | (unsigned)(exc + run));
            s_prefix = exc;
        }
    }
    __syncthreads();
    int run = (v - s) + woff[w] + s_prefix;
    g_off[base]     = run; g_cur[base]     = run; run += c.x;
    g_off[base + 1] = run; g_cur[base + 1] = run; run += c.y;
    g_off[base + 2] = run; g_cur[base + 2] = run; run += c.z;
    g_off[base + 3] = run; g_cur[base + 3] = run;
    if (blk == 0 && t == 0) g_off[NPAD] = E;
}

__global__ void k_fill(const int* __restrict__ ei, int E) {
    int e = blockIdx.x * blockDim.x + threadIdx.x;
    if (e >= E) return;
    int s = ei[e], d = ei[E + e];
    int slot = atomicAdd(&g_cur[d], 1);
    g_srcs[slot] = s;
}

// ---------------------------------------------------------------------------
// Persistent fused logmap0 + GEMM + bias + dinv[row] scale; fp16 h output.
// 3-term bf16 split (hh + hl + lh).
__global__ void __launch_bounds__(256, 2)
k_logmap_gemm(const float* __restrict__ x, const float* __restrict__ b,
              int N, int ntiles) {
    extern __shared__ __align__(16) char smraw[];
    __nv_bfloat16* swh = (__nv_bfloat16*)smraw;          // [128][LDSK]
    __nv_bfloat16* swl = swh + 128 * LDSK;
    __nv_bfloat16* sxh = swl + 128 * LDSK;               // [BM][LDSK]
    __nv_bfloat16* sxl = sxh + BM * LDSK;

    const int tid  = threadIdx.x;
    const int warp = tid >> 5, lane = tid & 31;

    for (int c = tid; c < 2048; c += 256) {
        int row = c >> 4, col8 = (c & 15) * 8;
        uint32_t sh = (uint32_t)__cvta_generic_to_shared(&swh[row * LDSK + col8]);
        cp_async16(sh, &g_wh[row * 128 + col8]);
        uint32_t sl = (uint32_t)__cvta_generic_to_shared(&swl[row * LDSK + col8]);
        cp_async16(sl, &g_wl[row * 128 + col8]);
    }
    asm volatile("cp.async.commit_group;");

    const int wm = warp & 3, wn = warp >> 2;
    const int m0 = wm * 16, n0b = wn * 64;
    const int mat = lane >> 3, mr = lane & 7;
    const int arow = m0 + mr + 8 * (mat & 1);
    const int aoff = 8 * (mat >> 1);
    uint32_t aBaseH = (uint32_t)__cvta_generic_to_shared(&sxh[arow * LDSK + aoff]);
    uint32_t aBaseL = (uint32_t)__cvta_generic_to_shared(&sxl[arow * LDSK + aoff]);
    uint32_t bBaseH[4], bBaseL[4];
#pragma unroll
    for (int g = 0; g < 4; g++) {
        int nrow = n0b + g * 16 + mr + 8 * (mat >> 1);
        int koff = 8 * (mat & 1);
        bBaseH[g] = (uint32_t)__cvta_generic_to_shared(&swh[nrow * LDSK + koff]);
        bBaseL[g] = (uint32_t)__cvta_generic_to_shared(&swl[nrow * LDSK + koff]);
    }

    bool wwait = true;
    const float4* x4 = (const float4*)x;

    for (int tile = blockIdx.x; tile < ntiles; tile += gridDim.x) {
        const int row0 = tile * BM;

#pragma unroll
        for (int rr = 0; rr < 8; rr++) {
            int r = warp * 8 + rr;
            int row = row0 + r;
            float4 v = (row < N) ? x4[row * 32 + lane] : make_float4(0.f, 0.f, 0.f, 0.f);
            float s = v.x * v.x + v.y * v.y + v.z * v.z + v.w * v.w;
#pragma unroll
            for (int off = 16; off; off >>= 1) s += __shfl_xor_sync(0xFFFFFFFFu, s, off);
            float norm = sqrtf(s);
            float nc = fminf(fmaxf(norm, 1e-15f), 1.0f - 1e-5f);
            // fast atanh: 0.5*log((1+nc)/(1-nc))
            float at = 0.5f * __logf(__fdividef(1.0f + nc, 1.0f - nc));
            float scale = __fdividef(at, fmaxf(norm, 1e-15f));
            v.x *= scale; v.y *= scale; v.z *= scale; v.w *= scale;
            __nv_bfloat16 h0 = __float2bfloat16_rn(v.x), h1 = __float2bfloat16_rn(v.y);
            __nv_bfloat16 h2 = __float2bfloat16_rn(v.z), h3 = __float2bfloat16_rn(v.w);
            __nv_bfloat16 l0 = __float2bfloat16_rn(v.x - __bfloat162float(h0));
            __nv_bfloat16 l1 = __float2bfloat16_rn(v.y - __bfloat162float(h1));
            __nv_bfloat16 l2 = __float2bfloat16_rn(v.z - __bfloat162float(h2));
            __nv_bfloat16 l3 = __float2bfloat16_rn(v.w - __bfloat162float(h3));
            int kc = lane * 4;
            __nv_bfloat162 hh0; hh0.x = h0; hh0.y = h1;
            __nv_bfloat162 hh1; hh1.x = h2; hh1.y = h3;
            __nv_bfloat162 ll0; ll0.x = l0; ll0.y = l1;
            __nv_bfloat162 ll1; ll1.x = l2; ll1.y = l3;
            *(__nv_bfloat162*)&sxh[r * LDSK + kc]     = hh0;
            *(__nv_bfloat162*)&sxh[r * LDSK + kc + 2] = hh1;
            *(__nv_bfloat162*)&sxl[r * LDSK + kc]     = ll0;
            *(__nv_bfloat162*)&sxl[r * LDSK + kc + 2] = ll1;
        }
        if (wwait) {
            asm volatile("cp.async.wait_group 0;");
            wwait = false;
        }
        __syncthreads();

        float acc[8][4];
#pragma unroll
        for (int f = 0; f < 8; f++)
#pragma unroll
            for (int j = 0; j < 4; j++) acc[f][j] = 0.f;

        uint32_t ah[2][4], al[2][4];
        uint32_t bh[2][4], bl[2][4];

        ldsm_x4(aBaseH, ah[0][0], ah[0][1], ah[0][2], ah[0][3]);
        ldsm_x4(aBaseL, al[0][0], al[0][1], al[0][2], al[0][3]);

#pragma unroll
        for (int kk = 0; kk < 8; kk++) {
            const uint32_t kb = kk * 32;
            const int cur = kk & 1, nxt = cur ^ 1;
            ldsm_x4(bBaseH[0] + kb, bh[0][0], bh[0][1], bh[0][2], bh[0][3]);
            ldsm_x4(bBaseL[0] + kb, bl[0][0], bl[0][1], bl[0][2], bl[0][3]);
            if (kk < 7) {
                ldsm_x4(aBaseH + kb + 32, ah[nxt][0], ah[nxt][1], ah[nxt][2], ah[nxt][3]);
                ldsm_x4(aBaseL + kb + 32, al[nxt][0], al[nxt][1], al[nxt][2], al[nxt][3]);
            }
#pragma unroll
            for (int g = 0; g < 4; g++) {
                const int gb = g & 1, gn = gb ^ 1;
                if (g < 3) {
                    ldsm_x4(bBaseH[g + 1] + kb, bh[gn][0], bh[gn][1], bh[gn][2], bh[gn][3]);
                    ldsm_x4(bBaseL[g + 1] + kb, bl[gn][0], bl[gn][1], bl[gn][2], bl[gn][3]);
                }
#pragma unroll
                for (int o = 0; o < 2; o++) {
                    const int f = 2 * g + o;
                    uint32_t b0h = bh[gb][2 * o], b1h = bh[gb][2 * o + 1];
                    uint32_t b0l = bl[gb][2 * o], b1l = bl[gb][2 * o + 1];
                    mma_bf16(acc[f], ah[cur], b0h, b1h);   // hh
                    mma_bf16(acc[f], ah[cur], b0l, b1l);   // hl
                    mma_bf16(acc[f], al[cur], b0h, b1h);   // lh (ll dropped)
                }
            }
        }
        __syncthreads();

        int r0r = row0 + m0 + (lane >> 2);
        int r1r = r0r + 8;
        float di0 = 0.f, di1 = 0.f;
        if (r0r < N) di0 = rsqrtf(fmaxf((float)(g_cin[r0r] + g_cout[r0r]), 1.0f));
        if (r1r < N) di1 = rsqrtf(fmaxf((float)(g_cin[r1r] + g_cout[r1r]), 1.0f));
        __half2* hp = (__half2*)g_h;
#pragma unroll
        for (int f = 0; f < 8; f++) {
            int c = n0b + f * 8 + 2 * (lane & 3);
            float bx = b[c], by = b[c + 1];
            if (r0r < N)
                hp[(r0r * DFEAT + c) >> 1] =
                    __floats2half2_rn((acc[f][0] + bx) * di0, (acc[f][1] + by) * di0);
            if (r1r < N)
                hp[(r1r * DFEAT + c) >> 1] =
                    __floats2half2_rn((acc[f][2] + bx) * di1, (acc[f][3] + by) * di1);
        }
    }
}

// ---------------------------------------------------------------------------
// CSR gather-sum (fp16 reads, fp32 accumulate) + dinv[dst] + fast expmap0.
// One warp per node; lane covers dims [4*lane, 4*lane+3] (uint2 = 4 halves).
__global__ void k_gather(float* __restrict__ out, int N) {
    int t = blockIdx.x * blockDim.x + threadIdx.x;
    if (t < SCANB) g_state[t] = 0ULL;
    int gw = t >> 5;
    int lane = threadIdx.x & 31;
    if (gw >= N) return;
    int beg = g_off[gw], end = g_off[gw + 1];
    const uint2* hh = (const uint2*)g_h;     // 32 uint2 per row

    float4 a0 = make_float4(0.f, 0.f, 0.f, 0.f);
    float4 a1 = make_float4(0.f, 0.f, 0.f, 0.f);
    int p = beg;
    for (; p + 4 <= end; p += 4) {
        int s0 = __ldg(&g_srcs[p]);
        int s1 = __ldg(&g_srcs[p + 1]);
        int s2 = __ldg(&g_srcs[p + 2]);
        int s3 = __ldg(&g_srcs[p + 3]);
        uint2 u0 = hh[s0 * 32 + lane];
        uint2 u1 = hh[s1 * 32 + lane];
        uint2 u2 = hh[s2 * 32 + lane];
        uint2 u3 = hh[s3 * 32 + lane];
        float2 f;
        f = __half22float2(*(__half2*)&u0.x); a0.x += f.x; a0.y += f.y;
        f = __half22float2(*(__half2*)&u0.y); a0.z += f.x; a0.w += f.y;
        f = __half22float2(*(__half2*)&u1.x); a1.x += f.x; a1.y += f.y;
        f = __half22float2(*(__half2*)&u1.y); a1.z += f.x; a1.w += f.y;
        f = __half22float2(*(__half2*)&u2.x); a0.x += f.x; a0.y += f.y;
        f = __half22float2(*(__half2*)&u2.y); a0.z += f.x; a0.w += f.y;
        f = __half22float2(*(__half2*)&u3.x); a1.x += f.x; a1.y += f.y;
        f = __half22float2(*(__half2*)&u3.y); a1.z += f.x; a1.w += f.y;
    }
    for (; p < end; p++) {
        int s0 = __ldg(&g_srcs[p]);
        uint2 u0 = hh[s0 * 32 + lane];
        float2 f;
        f = __half22float2(*(__half2*)&u0.x); a0.x += f.x; a0.y += f.y;
        f = __half22float2(*(__half2*)&u0.y); a0.z += f.x; a0.w += f.y;
    }
    float di = rsqrtf(fmaxf((float)(g_cin[gw] + g_cout[gw]), 1.0f));
    if (lane == 0) { g_cin[gw] = 0; g_cout[gw] = 0; }   // reset for next run
    float4 acc;
    acc.x = (a0.x + a1.x) * di;
    acc.y = (a0.y + a1.y) * di;
    acc.z = (a0.z + a1.z) * di;
    acc.w = (a0.w + a1.w) * di;

    float s = acc.x * acc.x + acc.y * acc.y + acc.z * acc.z + acc.w * acc.w;
#pragma unroll
    for (int off = 16; off; off >>= 1) s += __shfl_xor_sync(0xFFFFFFFFu, s, off);
    float norm = sqrtf(s);
    // fast tanh(norm)/norm
    float e2 = __expf(2.0f * norm);
    float scale = __fdividef(e2 - 1.0f, (e2 + 1.0f) * fmaxf(norm, 1e-15f));
    acc.x *= scale; acc.y *= scale; acc.z *= scale; acc.w *= scale;
    ((float4*)out)[gw * 32 + lane] = acc;
}

// ---------------------------------------------------------------------------
extern "C" void kernel_launch(void* const* d_in, const int* in_sizes, int n_in,
                              void* d_out, int out_size) {
    const float* x  = (const float*)d_in[0];
    const int*   ei = (const int*)d_in[1];
    const float* W  = (const float*)d_in[2];
    const float* b  = (const float*)d_in[3];
    float* out = (float*)d_out;

    const int N = in_sizes[0] / DFEAT;
    const int E = in_sizes[1] / 2;

    k_count<<<(E + 255) / 256, 256>>>(ei, W, E);
    k_scan<<<SCANB, 256>>>(E);
    k_fill<<<(E + 255) / 256, 256>>>(ei, E);
    {
        const int SMEM = (2 * 128 * LDSK + 2 * BM * LDSK) * (int)sizeof(__nv_bfloat16);
        cudaFuncSetAttribute(k_logmap_gemm,
                             cudaFuncAttributeMaxDynamicSharedMemorySize, SMEM);
        const int ntiles = (N + BM - 1) / BM;
        int grid = 296;
        if (grid > ntiles) grid = ntiles;
        k_logmap_gemm<<<grid, 256, SMEM>>>(x, b, N, ntiles);
    }
    {
        long long threads = (long long)N * 32;
        int grid = (int)((threads + 255) / 256);
        k_gather<<<grid, 256>>>(out, N);
    }
}

// round 14
// speedup vs baseline: 1.2513x; 1.0164x over previous
#include <cuda_runtime.h>
#include <cuda_bf16.h>
#include <cuda_fp16.h>
#include <cstdint>

#define DFEAT 128
#define NMAX  50000
#define NPAD  50176      // 49 * 1024
#define EMAX  600000
#define BM    64
#define LDSK  136        // smem row stride (bf16) -> 272B rows
#define SCANB 49

// scratch (no allocations allowed). Zero-initialized at load; k_gather's
// epilogue restores zeros each run (deterministic, graph-safe).
__device__ __align__(16) __half g_h[NMAX * DFEAT];    // fp16 features (12.8 MB)
__device__ __align__(16) int   g_cin[NPAD];
__device__ __align__(16) int   g_cout[NPAD];
__device__ __align__(16) int   g_off[NPAD + 1];
__device__ __align__(16) int   g_cur[NPAD];
__device__ __align__(16) int   g_srcs[EMAX];
__device__ __align__(16) unsigned long long g_state[SCANB];
__device__ __align__(16) __nv_bfloat16 g_wh[128 * 128];
__device__ __align__(16) __nv_bfloat16 g_wl[128 * 128];

__device__ __forceinline__ void ldsm_x4(uint32_t addr, uint32_t& r0, uint32_t& r1,
                                        uint32_t& r2, uint32_t& r3) {
    asm volatile("ldmatrix.sync.aligned.m8n8.x4.shared.b16 {%0,%1,%2,%3}, [%4];"
                 : "=r"(r0), "=r"(r1), "=r"(r2), "=r"(r3) : "r"(addr));
}

__device__ __forceinline__ void mma_bf16(float c[4], const uint32_t a[4],
                                         uint32_t b0, uint32_t b1) {
    asm volatile("mma.sync.aligned.m16n8k16.row.col.f32.bf16.bf16.f32 "
                 "{%0,%1,%2,%3},{%4,%5,%6,%7},{%8,%9},{%0,%1,%2,%3};"
                 : "+f"(c[0]), "+f"(c[1]), "+f"(c[2]), "+f"(c[3])
                 : "r"(a[0]), "r"(a[1]), "r"(a[2]), "r"(a[3]), "r"(b0), "r"(b1));
}

__device__ __forceinline__ void cp_async16(uint32_t saddr, const void* gptr) {
    asm volatile("cp.async.ca.shared.global [%0], [%1], 16;"
                 :: "r"(saddr), "l"(gptr) : "memory");
}

// ---------------------------------------------------------------------------
// degree count (counters pre-zeroed by previous run's gather) + W bf16 split
__global__ void k_count(const int* __restrict__ ei, const float* __restrict__ W, int E) {
    int e = blockIdx.x * blockDim.x + threadIdx.x;
    if (e < 128 * 128) {
        float w = W[e];
        __nv_bfloat16 h = __float2bfloat16_rn(w);
        g_wh[e] = h;
        g_wl[e] = __float2bfloat16_rn(w - __bfloat162float(h));
    }
    if (e >= E) return;
    atomicAdd(&g_cout[ei[e]], 1);        // src out-degree
    atomicAdd(&g_cin[ei[E + e]], 1);     // dst in-degree (= CSR count)
}

// ---------------------------------------------------------------------------
// Single-pass exclusive scan (decoupled lookback). 49 co-resident blocks.
__global__ void k_scan(int E) {
    __shared__ int woff[8];
    __shared__ int s_prefix;
    int blk = blockIdx.x, t = threadIdx.x;
    int lane = t & 31, w = t >> 5;
    int base = blk * 1024 + t * 4;
    int4 c = *(const int4*)&g_cin[base];
    int s = c.x + c.y + c.z + c.w;
    int v = s;
#pragma unroll
    for (int off = 1; off < 32; off <<= 1) {
        int u = __shfl_up_sync(0xFFFFFFFFu, v, off);
        if (lane >= off) v += u;
    }
    if (lane == 31) woff[w] = v;
    __syncthreads();
    if (t == 0) {
        int run = 0;
#pragma unroll
        for (int i = 0; i < 8; i++) { int x = woff[i]; woff[i] = run; run += x; }
        if (blk == 0) {
            atomicExch(&g_state[0], (2ULL << 32) | (unsigned)run);
            s_prefix = 0;
        } else {
            atomicExch(&g_state[blk], (1ULL << 32) | (unsigned)run);
            int exc = 0;
            int p = blk - 1;
            while (p >= 0) {
                unsigned long long st = atomicAdd(&g_state[p], 0ULL);
                unsigned flag = (unsigned)(st >> 32);
                if (flag == 2u) { exc += (int)(st & 0xFFFFFFFFu); break; }
                if (flag == 1u) { exc += (int)(st & 0xFFFFFFFFu); p--; }
            }
            atomicExch(&g_state[blk], (2ULL << 32) | (unsigned)(exc + run));
            s_prefix = exc;
        }
    }
    __syncthreads();
    int run = (v - s) + woff[w] + s_prefix;
    g_off[base]     = run; g_cur[base]     = run; run += c.x;
    g_off[base + 1] = run; g_cur[base + 1] = run; run += c.y;
    g_off[base + 2] = run; g_cur[base + 2] = run; run += c.z;
    g_off[base + 3] = run; g_cur[base + 3] = run;
    if (blk == 0 && t == 0) g_off[NPAD] = E;
}

__global__ void k_fill(const int* __restrict__ ei, int E) {
    int e = blockIdx.x * blockDim.x + threadIdx.x;
    if (e >= E) return;
    int s = ei[e], d = ei[E + e];
    int slot = atomicAdd(&g_cur[d], 1);
    g_srcs[slot] = s;
}

// ---------------------------------------------------------------------------
// Persistent fused GEMM on RAW x; logmap scale + bias + dinv in epilogue.
//   h[r] = (scale_r * (x_r @ W^T) + b) * dinv_r,  scale_r = atanh(||x_r||)/||x_r||
// Norm reductions run AFTER the smem-ready sync, overlapped with MMA.
__global__ void __launch_bounds__(256, 2)
k_logmap_gemm(const float* __restrict__ x, const float* __restrict__ b,
              int N, int ntiles) {
    extern __shared__ __align__(16) char smraw[];
    __nv_bfloat16* swh = (__nv_bfloat16*)smraw;          // [128][LDSK]
    __nv_bfloat16* swl = swh + 128 * LDSK;
    __nv_bfloat16* sxh = swl + 128 * LDSK;               // [BM][LDSK]
    __nv_bfloat16* sxl = sxh + BM * LDSK;
    float* s_scale = (float*)(sxl + BM * LDSK);          // [BM] per-row logmap scale

    const int tid  = threadIdx.x;
    const int warp = tid >> 5, lane = tid & 31;

    for (int c = tid; c < 2048; c += 256) {
        int row = c >> 4, col8 = (c & 15) * 8;
        uint32_t sh = (uint32_t)__cvta_generic_to_shared(&swh[row * LDSK + col8]);
        cp_async16(sh, &g_wh[row * 128 + col8]);
        uint32_t sl = (uint32_t)__cvta_generic_to_shared(&swl[row * LDSK + col8]);
        cp_async16(sl, &g_wl[row * 128 + col8]);
    }
    asm volatile("cp.async.commit_group;");

    const int wm = warp & 3, wn = warp >> 2;
    const int m0 = wm * 16, n0b = wn * 64;
    const int mat = lane >> 3, mr = lane & 7;
    const int arow = m0 + mr + 8 * (mat & 1);
    const int aoff = 8 * (mat >> 1);
    uint32_t aBaseH = (uint32_t)__cvta_generic_to_shared(&sxh[arow * LDSK + aoff]);
    uint32_t aBaseL = (uint32_t)__cvta_generic_to_shared(&sxl[arow * LDSK + aoff]);
    uint32_t bBaseH[4], bBaseL[4];
#pragma unroll
    for (int g = 0; g < 4; g++) {
        int nrow = n0b + g * 16 + mr + 8 * (mat >> 1);
        int koff = 8 * (mat & 1);
        bBaseH[g] = (uint32_t)__cvta_generic_to_shared(&swh[nrow * LDSK + koff]);
        bBaseL[g] = (uint32_t)__cvta_generic_to_shared(&swl[nrow * LDSK + koff]);
    }

    bool wwait = true;
    const float4* x4 = (const float4*)x;

    for (int tile = blockIdx.x; tile < ntiles; tile += gridDim.x) {
        const int row0 = tile * BM;

        // ---- x-phase: load raw rows, split hi/lo, store (NO reduction) ----
        float4 vbuf[8];
#pragma unroll
        for (int rr = 0; rr < 8; rr++) {
            int r = warp * 8 + rr;
            int row = row0 + r;
            float4 v = (row < N) ? x4[row * 32 + lane] : make_float4(0.f, 0.f, 0.f, 0.f);
            vbuf[rr] = v;
            __nv_bfloat16 h0 = __float2bfloat16_rn(v.x), h1 = __float2bfloat16_rn(v.y);
            __nv_bfloat16 h2 = __float2bfloat16_rn(v.z), h3 = __float2bfloat16_rn(v.w);
            __nv_bfloat16 l0 = __float2bfloat16_rn(v.x - __bfloat162float(h0));
            __nv_bfloat16 l1 = __float2bfloat16_rn(v.y - __bfloat162float(h1));
            __nv_bfloat16 l2 = __float2bfloat16_rn(v.z - __bfloat162float(h2));
            __nv_bfloat16 l3 = __float2bfloat16_rn(v.w - __bfloat162float(h3));
            int kc = lane * 4;
            __nv_bfloat162 hh0; hh0.x = h0; hh0.y = h1;
            __nv_bfloat162 hh1; hh1.x = h2; hh1.y = h3;
            __nv_bfloat162 ll0; ll0.x = l0; ll0.y = l1;
            __nv_bfloat162 ll1; ll1.x = l2; ll1.y = l3;
            *(__nv_bfloat162*)&sxh[r * LDSK + kc]     = hh0;
            *(__nv_bfloat162*)&sxh[r * LDSK + kc + 2] = hh1;
            *(__nv_bfloat162*)&sxl[r * LDSK + kc]     = ll0;
            *(__nv_bfloat162*)&sxl[r * LDSK + kc + 2] = ll1;
        }
        if (wwait) {
            asm volatile("cp.async.wait_group 0;");
            wwait = false;
        }
        __syncthreads();

        // ---- norm/scale computation: overlaps with MMA phase below.
        // s_scale written here, consumed only after the post-MMA sync.
#pragma unroll
        for (int rr = 0; rr < 8; rr++) {
            float4 v = vbuf[rr];
            float s = v.x * v.x + v.y * v.y + v.z * v.z + v.w * v.w;
#pragma unroll
            for (int off = 16; off; off >>= 1) s += __shfl_xor_sync(0xFFFFFFFFu, s, off);
            float norm = sqrtf(s);
            float nc = fminf(fmaxf(norm, 1e-15f), 1.0f - 1e-5f);
            float at = 0.5f * __logf(__fdividef(1.0f + nc, 1.0f - nc));
            float scale = __fdividef(at, fmaxf(norm, 1e-15f));
            if (lane == 0) s_scale[warp * 8 + rr] = scale;
        }

        // ---- MMA mainloop (raw x) ----
        float acc[8][4];
#pragma unroll
        for (int f = 0; f < 8; f++)
#pragma unroll
            for (int j = 0; j < 4; j++) acc[f][j] = 0.f;

        uint32_t ah[2][4], al[2][4];
        uint32_t bh[2][4], bl[2][4];

        ldsm_x4(aBaseH, ah[0][0], ah[0][1], ah[0][2], ah[0][3]);
        ldsm_x4(aBaseL, al[0][0], al[0][1], al[0][2], al[0][3]);

#pragma unroll
        for (int kk = 0; kk < 8; kk++) {
            const uint32_t kb = kk * 32;
            const int cur = kk & 1, nxt = cur ^ 1;
            ldsm_x4(bBaseH[0] + kb, bh[0][0], bh[0][1], bh[0][2], bh[0][3]);
            ldsm_x4(bBaseL[0] + kb, bl[0][0], bl[0][1], bl[0][2], bl[0][3]);
            if (kk < 7) {
                ldsm_x4(aBaseH + kb + 32, ah[nxt][0], ah[nxt][1], ah[nxt][2], ah[nxt][3]);
                ldsm_x4(aBaseL + kb + 32, al[nxt][0], al[nxt][1], al[nxt][2], al[nxt][3]);
            }
#pragma unroll
            for (int g = 0; g < 4; g++) {
                const int gb = g & 1, gn = gb ^ 1;
                if (g < 3) {
                    ldsm_x4(bBaseH[g + 1] + kb, bh[gn][0], bh[gn][1], bh[gn][2], bh[gn][3]);
                    ldsm_x4(bBaseL[g + 1] + kb, bl[gn][0], bl[gn][1], bl[gn][2], bl[gn][3]);
                }
#pragma unroll
                for (int o = 0; o < 2; o++) {
                    const int f = 2 * g + o;
                    uint32_t b0h = bh[gb][2 * o], b1h = bh[gb][2 * o + 1];
                    uint32_t b0l = bl[gb][2 * o], b1l = bl[gb][2 * o + 1];
                    mma_bf16(acc[f], ah[cur], b0h, b1h);   // hh
                    mma_bf16(acc[f], ah[cur], b0l, b1l);   // hl
                    mma_bf16(acc[f], al[cur], b0h, b1h);   // lh (ll dropped)
                }
            }
        }
        __syncthreads();   // MMA + s_scale writes complete

        // ---- epilogue: *scale_r, +bias, *dinv_r, fp16 store ----
        int lr0 = m0 + (lane >> 2);
        int lr1 = lr0 + 8;
        int r0r = row0 + lr0;
        int r1r = r0r + 8;
        float sc0 = s_scale[lr0], sc1 = s_scale[lr1];
        float di0 = 0.f, di1 = 0.f;
        if (r0r < N) di0 = rsqrtf(fmaxf((float)(g_cin[r0r] + g_cout[r0r]), 1.0f));
        if (r1r < N) di1 = rsqrtf(fmaxf((float)(g_cin[r1r] + g_cout[r1r]), 1.0f));
        __half2* hp = (__half2*)g_h;
#pragma unroll
        for (int f = 0; f < 8; f++) {
            int c = n0b + f * 8 + 2 * (lane & 3);
            float bx = b[c], by = b[c + 1];
            if (r0r < N)
                hp[(r0r * DFEAT + c) >> 1] =
                    __floats2half2_rn((acc[f][0] * sc0 + bx) * di0,
                                      (acc[f][1] * sc0 + by) * di0);
            if (r1r < N)
                hp[(r1r * DFEAT + c) >> 1] =
                    __floats2half2_rn((acc[f][2] * sc1 + bx) * di1,
                                      (acc[f][3] * sc1 + by) * di1);
        }
        __syncthreads();   // epilogue read of s_scale done; safe to refill
    }
}

// ---------------------------------------------------------------------------
// CSR gather-sum (fp16 reads, fp32 accumulate) + dinv[dst] + fast expmap0.
__global__ void k_gather(float* __restrict__ out, int N) {
    int t = blockIdx.x * blockDim.x + threadIdx.x;
    if (t < SCANB) g_state[t] = 0ULL;
    int gw = t >> 5;
    int lane = threadIdx.x & 31;
    if (gw >= N) return;
    int beg = g_off[gw], end = g_off[gw + 1];
    const uint2* hh = (const uint2*)g_h;     // 32 uint2 per row

    float4 a0 = make_float4(0.f, 0.f, 0.f, 0.f);
    float4 a1 = make_float4(0.f, 0.f, 0.f, 0.f);
    int p = beg;
    for (; p + 4 <= end; p += 4) {
        int s0 = __ldg(&g_srcs[p]);
        int s1 = __ldg(&g_srcs[p + 1]);
        int s2 = __ldg(&g_srcs[p + 2]);
        int s3 = __ldg(&g_srcs[p + 3]);
        uint2 u0 = hh[s0 * 32 + lane];
        uint2 u1 = hh[s1 * 32 + lane];
        uint2 u2 = hh[s2 * 32 + lane];
        uint2 u3 = hh[s3 * 32 + lane];
        float2 f;
        f = __half22float2(*(__half2*)&u0.x); a0.x += f.x; a0.y += f.y;
        f = __half22float2(*(__half2*)&u0.y); a0.z += f.x; a0.w += f.y;
        f = __half22float2(*(__half2*)&u1.x); a1.x += f.x; a1.y += f.y;
        f = __half22float2(*(__half2*)&u1.y); a1.z += f.x; a1.w += f.y;
        f = __half22float2(*(__half2*)&u2.x); a0.x += f.x; a0.y += f.y;
        f = __half22float2(*(__half2*)&u2.y); a0.z += f.x; a0.w += f.y;
        f = __half22float2(*(__half2*)&u3.x); a1.x += f.x; a1.y += f.y;
        f = __half22float2(*(__half2*)&u3.y); a1.z += f.x; a1.w += f.y;
    }
    for (; p < end; p++) {
        int s0 = __ldg(&g_srcs[p]);
        uint2 u0 = hh[s0 * 32 + lane];
        float2 f;
        f = __half22float2(*(__half2*)&u0.x); a0.x += f.x; a0.y += f.y;
        f = __half22float2(*(__half2*)&u0.y); a0.z += f.x; a0.w += f.y;
    }
    float di = rsqrtf(fmaxf((float)(g_cin[gw] + g_cout[gw]), 1.0f));
    if (lane == 0) { g_cin[gw] = 0; g_cout[gw] = 0; }   // reset for next run
    float4 acc;
    acc.x = (a0.x + a1.x) * di;
    acc.y = (a0.y + a1.y) * di;
    acc.z = (a0.z + a1.z) * di;
    acc.w = (a0.w + a1.w) * di;

    float s = acc.x * acc.x + acc.y * acc.y + acc.z * acc.z + acc.w * acc.w;
#pragma unroll
    for (int off = 16; off; off >>= 1) s += __shfl_xor_sync(0xFFFFFFFFu, s, off);
    float norm = sqrtf(s);
    float e2 = __expf(2.0f * norm);
    float scale = __fdividef(e2 - 1.0f, (e2 + 1.0f) * fmaxf(norm, 1e-15f));
    acc.x *= scale; acc.y *= scale; acc.z *= scale; acc.w *= scale;
    ((float4*)out)[gw * 32 + lane] = acc;
}

// ---------------------------------------------------------------------------
extern "C" void kernel_launch(void* const* d_in, const int* in_sizes, int n_in,
                              void* d_out, int out_size) {
    const float* x  = (const float*)d_in[0];
    const int*   ei = (const int*)d_in[1];
    const float* W  = (const float*)d_in[2];
    const float* b  = (const float*)d_in[3];
    float* out = (float*)d_out;

    const int N = in_sizes[0] / DFEAT;
    const int E = in_sizes[1] / 2;

    k_count<<<(E + 255) / 256, 256>>>(ei, W, E);
    k_scan<<<SCANB, 256>>>(E);
    k_fill<<<(E + 255) / 256, 256>>>(ei, E);
    {
        const int SMEM = (2 * 128 * LDSK + 2 * BM * LDSK) * (int)sizeof(__nv_bfloat16)
                       + BM * (int)sizeof(float);
        cudaFuncSetAttribute(k_logmap_gemm,
                             cudaFuncAttributeMaxDynamicSharedMemorySize, SMEM);
        const int ntiles = (N + BM - 1) / BM;
        int grid = 296;
        if (grid > ntiles) grid = ntiles;
        k_logmap_gemm<<<grid, 256, SMEM>>>(x, b, N, ntiles);
    }
    {
        long long threads = (long long)N * 32;
        int grid = (int)((threads + 255) / 256);
        k_gather<<<grid, 256>>>(out, N);
    }
}

// round 15
// speedup vs baseline: 1.3597x; 1.0867x over previous
#include <cuda_runtime.h>
#include <cuda_bf16.h>
#include <cuda_fp16.h>
#include <cstdint>

#define DFEAT 128
#define NMAX  50000
#define NPAD  50176      // 49 * 1024
#define EMAX  600000
#define BM    64
#define LDSK  136        // smem row stride (bf16) -> 272B rows
#define SCANB 49

// scratch (no allocations allowed). Zero-initialized at load; k_gather's
// epilogue restores zeros each run (deterministic, graph-safe).
__device__ __align__(16) __half g_h[NMAX * DFEAT];    // fp16 features (12.8 MB)
__device__ __align__(16) int   g_cin[NPAD];
__device__ __align__(16) int   g_cout[NPAD];
__device__ __align__(16) int   g_off[NPAD + 1];
__device__ __align__(16) int   g_cur[NPAD];
__device__ __align__(16) int   g_srcs[EMAX];
__device__ __align__(16) unsigned long long g_state[SCANB];
__device__ __align__(16) __nv_bfloat16 g_wh[128 * 128];
__device__ __align__(16) __nv_bfloat16 g_wl[128 * 128];

__device__ __forceinline__ void ldsm_x4(uint32_t addr, uint32_t& r0, uint32_t& r1,
                                        uint32_t& r2, uint32_t& r3) {
    asm volatile("ldmatrix.sync.aligned.m8n8.x4.shared.b16 {%0,%1,%2,%3}, [%4];"
                 : "=r"(r0), "=r"(r1), "=r"(r2), "=r"(r3) : "r"(addr));
}

__device__ __forceinline__ void mma_bf16(float c[4], const uint32_t a[4],
                                         uint32_t b0, uint32_t b1) {
    asm volatile("mma.sync.aligned.m16n8k16.row.col.f32.bf16.bf16.f32 "
                 "{%0,%1,%2,%3},{%4,%5,%6,%7},{%8,%9},{%0,%1,%2,%3};"
                 : "+f"(c[0]), "+f"(c[1]), "+f"(c[2]), "+f"(c[3])
                 : "r"(a[0]), "r"(a[1]), "r"(a[2]), "r"(a[3]), "r"(b0), "r"(b1));
}

__device__ __forceinline__ void cp_async16(uint32_t saddr, const void* gptr) {
    asm volatile("cp.async.ca.shared.global [%0], [%1], 16;"
                 :: "r"(saddr), "l"(gptr) : "memory");
}

// ---------------------------------------------------------------------------
// degree count (counters pre-zeroed by previous run's gather) + W bf16 split
__global__ void k_count(const int* __restrict__ ei, const float* __restrict__ W, int E) {
    int e = blockIdx.x * blockDim.x + threadIdx.x;
    if (e < 128 * 128) {
        float w = W[e];
        __nv_bfloat16 h = __float2bfloat16_rn(w);
        g_wh[e] = h;
        g_wl[e] = __float2bfloat16_rn(w - __bfloat162float(h));
    }
    if (e >= E) return;
    atomicAdd(&g_cout[ei[e]], 1);        // src out-degree
    atomicAdd(&g_cin[ei[E + e]], 1);     // dst in-degree (= CSR count)
}

// ---------------------------------------------------------------------------
// Single-pass exclusive scan (decoupled lookback). 49 co-resident blocks.
__global__ void k_scan(int E) {
    __shared__ int woff[8];
    __shared__ int s_prefix;
    int blk = blockIdx.x, t = threadIdx.x;
    int lane = t & 31, w = t >> 5;
    int base = blk * 1024 + t * 4;
    int4 c = *(const int4*)&g_cin[base];
    int s = c.x + c.y + c.z + c.w;
    int v = s;
#pragma unroll
    for (int off = 1; off < 32; off <<= 1) {
        int u = __shfl_up_sync(0xFFFFFFFFu, v, off);
        if (lane >= off) v += u;
    }
    if (lane == 31) woff[w] = v;
    __syncthreads();
    if (t == 0) {
        int run = 0;
#pragma unroll
        for (int i = 0; i < 8; i++) { int x = woff[i]; woff[i] = run; run += x; }
        if (blk == 0) {
            atomicExch(&g_state[0], (2ULL << 32) | (unsigned)run);
            s_prefix = 0;
        } else {
            atomicExch(&g_state[blk], (1ULL << 32) | (unsigned)run);
            int exc = 0;
            int p = blk - 1;
            while (p >= 0) {
                unsigned long long st = atomicAdd(&g_state[p], 0ULL);
                unsigned flag = (unsigned)(st >> 32);
                if (flag == 2u) { exc += (int)(st & 0xFFFFFFFFu); break; }
                if (flag == 1u) { exc += (int)(st & 0xFFFFFFFFu); p--; }
            }
            atomicExch(&g_state[blk], (2ULL << 32) | (unsigned)(exc + run));
            s_prefix = exc;
        }
    }
    __syncthreads();
    int run = (v - s) + woff[w] + s_prefix;
    g_off[base]     = run; g_cur[base]     = run; run += c.x;
    g_off[base + 1] = run; g_cur[base + 1] = run; run += c.y;
    g_off[base + 2] = run; g_cur[base + 2] = run; run += c.z;
    g_off[base + 3] = run; g_cur[base + 3] = run;
    if (blk == 0 && t == 0) g_off[NPAD] = E;
}

__global__ void k_fill(const int* __restrict__ ei, int E) {
    int e = blockIdx.x * blockDim.x + threadIdx.x;
    if (e >= E) return;
    int s = ei[e], d = ei[E + e];
    int slot = atomicAdd(&g_cur[d], 1);
    g_srcs[slot] = s;
}

// ---------------------------------------------------------------------------
// Persistent fused GEMM on RAW x; logmap scale + bias + dinv in epilogue.
__global__ void __launch_bounds__(256, 2)
k_logmap_gemm(const float* __restrict__ x, const float* __restrict__ b,
              int N, int ntiles) {
    extern __shared__ __align__(16) char smraw[];
    __nv_bfloat16* swh = (__nv_bfloat16*)smraw;          // [128][LDSK]
    __nv_bfloat16* swl = swh + 128 * LDSK;
    __nv_bfloat16* sxh = swl + 128 * LDSK;               // [BM][LDSK]
    __nv_bfloat16* sxl = sxh + BM * LDSK;
    float* s_scale = (float*)(sxl + BM * LDSK);          // [BM] logmap scales

    const int tid  = threadIdx.x;
    const int warp = tid >> 5, lane = tid & 31;

    for (int c = tid; c < 2048; c += 256) {
        int row = c >> 4, col8 = (c & 15) * 8;
        uint32_t sh = (uint32_t)__cvta_generic_to_shared(&swh[row * LDSK + col8]);
        cp_async16(sh, &g_wh[row * 128 + col8]);
        uint32_t sl = (uint32_t)__cvta_generic_to_shared(&swl[row * LDSK + col8]);
        cp_async16(sl, &g_wl[row * 128 + col8]);
    }
    asm volatile("cp.async.commit_group;");

    const int wm = warp & 3, wn = warp >> 2;
    const int m0 = wm * 16, n0b = wn * 64;
    const int mat = lane >> 3, mr = lane & 7;
    const int arow = m0 + mr + 8 * (mat & 1);
    const int aoff = 8 * (mat >> 1);
    uint32_t aBaseH = (uint32_t)__cvta_generic_to_shared(&sxh[arow * LDSK + aoff]);
    uint32_t aBaseL = (uint32_t)__cvta_generic_to_shared(&sxl[arow * LDSK + aoff]);
    uint32_t bBaseH[4], bBaseL[4];
#pragma unroll
    for (int g = 0; g < 4; g++) {
        int nrow = n0b + g * 16 + mr + 8 * (mat >> 1);
        int koff = 8 * (mat & 1);
        bBaseH[g] = (uint32_t)__cvta_generic_to_shared(&swh[nrow * LDSK + koff]);
        bBaseL[g] = (uint32_t)__cvta_generic_to_shared(&swl[nrow * LDSK + koff]);
    }

    bool wwait = true;
    const float4* x4 = (const float4*)x;

    for (int tile = blockIdx.x; tile < ntiles; tile += gridDim.x) {
        const int row0 = tile * BM;

        // ---- x-phase: load raw rows, split hi/lo, store (NO reduction) ----
        float4 vbuf[8];
#pragma unroll
        for (int rr = 0; rr < 8; rr++) {
            int r = warp * 8 + rr;
            int row = row0 + r;
            float4 v = (row < N) ? x4[row * 32 + lane] : make_float4(0.f, 0.f, 0.f, 0.f);
            vbuf[rr] = v;
            __nv_bfloat16 h0 = __float2bfloat16_rn(v.x), h1 = __float2bfloat16_rn(v.y);
            __nv_bfloat16 h2 = __float2bfloat16_rn(v.z), h3 = __float2bfloat16_rn(v.w);
            __nv_bfloat16 l0 = __float2bfloat16_rn(v.x - __bfloat162float(h0));
            __nv_bfloat16 l1 = __float2bfloat16_rn(v.y - __bfloat162float(h1));
            __nv_bfloat16 l2 = __float2bfloat16_rn(v.z - __bfloat162float(h2));
            __nv_bfloat16 l3 = __float2bfloat16_rn(v.w - __bfloat162float(h3));
            int kc = lane * 4;
            __nv_bfloat162 hh0; hh0.x = h0; hh0.y = h1;
            __nv_bfloat162 hh1; hh1.x = h2; hh1.y = h3;
            __nv_bfloat162 ll0; ll0.x = l0; ll0.y = l1;
            __nv_bfloat162 ll1; ll1.x = l2; ll1.y = l3;
            *(__nv_bfloat162*)&sxh[r * LDSK + kc]     = hh0;
            *(__nv_bfloat162*)&sxh[r * LDSK + kc + 2] = hh1;
            *(__nv_bfloat162*)&sxl[r * LDSK + kc]     = ll0;
            *(__nv_bfloat162*)&sxl[r * LDSK + kc + 2] = ll1;
        }
        if (wwait) {
            asm volatile("cp.async.wait_group 0;");
            wwait = false;
        }
        __syncthreads();

        // ---- norm/scale: overlapped with MMA, consumed after post-MMA sync
#pragma unroll
        for (int rr = 0; rr < 8; rr++) {
            float4 v = vbuf[rr];
            float s = v.x * v.x + v.y * v.y + v.z * v.z + v.w * v.w;
#pragma unroll
            for (int off = 16; off; off >>= 1) s += __shfl_xor_sync(0xFFFFFFFFu, s, off);
            float norm = sqrtf(s);
            float nc = fminf(fmaxf(norm, 1e-15f), 1.0f - 1e-5f);
            float at = 0.5f * __logf(__fdividef(1.0f + nc, 1.0f - nc));
            float scale = __fdividef(at, fmaxf(norm, 1e-15f));
            if (lane == 0) s_scale[warp * 8 + rr] = scale;
        }

        // ---- MMA mainloop ----
        float acc[8][4];
#pragma unroll
        for (int f = 0; f < 8; f++)
#pragma unroll
            for (int j = 0; j < 4; j++) acc[f][j] = 0.f;

        uint32_t ah[2][4], al[2][4];
        uint32_t bh[2][4], bl[2][4];

        ldsm_x4(aBaseH, ah[0][0], ah[0][1], ah[0][2], ah[0][3]);
        ldsm_x4(aBaseL, al[0][0], al[0][1], al[0][2], al[0][3]);

#pragma unroll
        for (int kk = 0; kk < 8; kk++) {
            const uint32_t kb = kk * 32;
            const int cur = kk & 1, nxt = cur ^ 1;
            ldsm_x4(bBaseH[0] + kb, bh[0][0], bh[0][1], bh[0][2], bh[0][3]);
            ldsm_x4(bBaseL[0] + kb, bl[0][0], bl[0][1], bl[0][2], bl[0][3]);
            if (kk < 7) {
                ldsm_x4(aBaseH + kb + 32, ah[nxt][0], ah[nxt][1], ah[nxt][2], ah[nxt][3]);
                ldsm_x4(aBaseL + kb + 32, al[nxt][0], al[nxt][1], al[nxt][2], al[nxt][3]);
            }
#pragma unroll
            for (int g = 0; g < 4; g++) {
                const int gb = g & 1, gn = gb ^ 1;
                if (g < 3) {
                    ldsm_x4(bBaseH[g + 1] + kb, bh[gn][0], bh[gn][1], bh[gn][2], bh[gn][3]);
                    ldsm_x4(bBaseL[g + 1] + kb, bl[gn][0], bl[gn][1], bl[gn][2], bl[gn][3]);
                }
#pragma unroll
                for (int o = 0; o < 2; o++) {
                    const int f = 2 * g + o;
                    uint32_t b0h = bh[gb][2 * o], b1h = bh[gb][2 * o + 1];
                    uint32_t b0l = bl[gb][2 * o], b1l = bl[gb][2 * o + 1];
                    mma_bf16(acc[f], ah[cur], b0h, b1h);   // hh
                    mma_bf16(acc[f], ah[cur], b0l, b1l);   // hl
                    mma_bf16(acc[f], al[cur], b0h, b1h);   // lh (ll dropped)
                }
            }
        }
        __syncthreads();   // MMA + s_scale writes complete

        // ---- epilogue: *scale_r, +bias, *dinv_r, fp16 store ----
        int lr0 = m0 + (lane >> 2);
        int lr1 = lr0 + 8;
        int r0r = row0 + lr0;
        int r1r = r0r + 8;
        float sc0 = s_scale[lr0], sc1 = s_scale[lr1];
        float di0 = 0.f, di1 = 0.f;
        if (r0r < N) di0 = rsqrtf(fmaxf((float)(g_cin[r0r] + g_cout[r0r]), 1.0f));
        if (r1r < N) di1 = rsqrtf(fmaxf((float)(g_cin[r1r] + g_cout[r1r]), 1.0f));
        __half2* hp = (__half2*)g_h;
#pragma unroll
        for (int f = 0; f < 8; f++) {
            int c = n0b + f * 8 + 2 * (lane & 3);
            float bx = b[c], by = b[c + 1];
            if (r0r < N)
                hp[(r0r * DFEAT + c) >> 1] =
                    __floats2half2_rn((acc[f][0] * sc0 + bx) * di0,
                                      (acc[f][1] * sc0 + by) * di0);
            if (r1r < N)
                hp[(r1r * DFEAT + c) >> 1] =
                    __floats2half2_rn((acc[f][2] * sc1 + bx) * di1,
                                      (acc[f][3] * sc1 + by) * di1);
        }
        __syncthreads();   // epilogue read of s_scale done; safe to refill
    }
}

// ---------------------------------------------------------------------------
// CSR gather-sum (fp16 reads, fp32 accumulate) + dinv[dst] + fast expmap0.
__global__ void k_gather(float* __restrict__ out, int N) {
    int t = blockIdx.x * blockDim.x + threadIdx.x;
    if (t < SCANB) g_state[t] = 0ULL;
    int gw = t >> 5;
    int lane = threadIdx.x & 31;
    if (gw >= N) return;
    int beg = g_off[gw], end = g_off[gw + 1];
    const uint2* hh = (const uint2*)g_h;     // 32 uint2 per row

    float4 a0 = make_float4(0.f, 0.f, 0.f, 0.f);
    float4 a1 = make_float4(0.f, 0.f, 0.f, 0.f);
    int p = beg;
    for (; p + 4 <= end; p += 4) {
        int s0 = __ldg(&g_srcs[p]);
        int s1 = __ldg(&g_srcs[p + 1]);
        int s2 = __ldg(&g_srcs[p + 2]);
        int s3 = __ldg(&g_srcs[p + 3]);
        uint2 u0 = hh[s0 * 32 + lane];
        uint2 u1 = hh[s1 * 32 + lane];
        uint2 u2 = hh[s2 * 32 + lane];
        uint2 u3 = hh[s3 * 32 + lane];
        float2 f;
        f = __half22float2(*(__half2*)&u0.x); a0.x += f.x; a0.y += f.y;
        f = __half22float2(*(__half2*)&u0.y); a0.z += f.x; a0.w += f.y;
        f = __half22float2(*(__half2*)&u1.x); a1.x += f.x; a1.y += f.y;
        f = __half22float2(*(__half2*)&u1.y); a1.z += f.x; a1.w += f.y;
        f = __half22float2(*(__half2*)&u2.x); a0.x += f.x; a0.y += f.y;
        f = __half22float2(*(__half2*)&u2.y); a0.z += f.x; a0.w += f.y;
        f = __half22float2(*(__half2*)&u3.x); a1.x += f.x; a1.y += f.y;
        f = __half22float2(*(__half2*)&u3.y); a1.z += f.x; a1.w += f.y;
    }
    for (; p < end; p++) {
        int s0 = __ldg(&g_srcs[p]);
        uint2 u0 = hh[s0 * 32 + lane];
        float2 f;
        f = __half22float2(*(__half2*)&u0.x); a0.x += f.x; a0.y += f.y;
        f = __half22float2(*(__half2*)&u0.y); a0.z += f.x; a0.w += f.y;
    }
    float di = rsqrtf(fmaxf((float)(g_cin[gw] + g_cout[gw]), 1.0f));
    if (lane == 0) { g_cin[gw] = 0; g_cout[gw] = 0; }   // reset for next run
    float4 acc;
    acc.x = (a0.x + a1.x) * di;
    acc.y = (a0.y + a1.y) * di;
    acc.z = (a0.z + a1.z) * di;
    acc.w = (a0.w + a1.w) * di;

    float s = acc.x * acc.x + acc.y * acc.y + acc.z * acc.z + acc.w * acc.w;
#pragma unroll
    for (int off = 16; off; off >>= 1) s += __shfl_xor_sync(0xFFFFFFFFu, s, off);
    float norm = sqrtf(s);
    float e2 = __expf(2.0f * norm);
    float scale = __fdividef(e2 - 1.0f, (e2 + 1.0f) * fmaxf(norm, 1e-15f));
    acc.x *= scale; acc.y *= scale; acc.z *= scale; acc.w *= scale;
    ((float4*)out)[gw * 32 + lane] = acc;
}

// ---------------------------------------------------------------------------
extern "C" void kernel_launch(void* const* d_in, const int* in_sizes, int n_in,
                              void* d_out, int out_size) {
    const float* x  = (const float*)d_in[0];
    const int*   ei = (const int*)d_in[1];
    const float* W  = (const float*)d_in[2];
    const float* b  = (const float*)d_in[3];
    float* out = (float*)d_out;

    const int N = in_sizes[0] / DFEAT;
    const int E = in_sizes[1] / 2;

    // lazy-created side stream + fork/join events (host objects; no device mem).
    // Same launches every call -> deterministic, graph-capture-legal fork/join.
    static cudaStream_t sB = nullptr;
    static cudaEvent_t evC = nullptr, evB = nullptr;
    if (sB == nullptr) {
        cudaStreamCreateWithFlags(&sB, cudaStreamNonBlocking);
        cudaEventCreateWithFlags(&evC, cudaEventDisableTiming);
        cudaEventCreateWithFlags(&evB, cudaEventDisableTiming);
    }

    // 1. count (produces cin/cout needed by BOTH branches)
    k_count<<<(E + 255) / 256, 256>>>(ei, W, E);
    cudaEventRecord(evC, 0);

    // 2a. side stream: scan -> fill (outputs consumed only by gather)
    cudaStreamWaitEvent(sB, evC, 0);
    k_scan<<<SCANB, 256, 0, sB>>>(E);
    k_fill<<<(E + 255) / 256, 256, 0, sB>>>(ei, E);
    cudaEventRecord(evB, sB);

    // 2b. main stream: GEMM (needs only cin/cout) — overlaps with scan+fill
    {
        const int SMEM = (2 * 128 * LDSK + 2 * BM * LDSK) * (int)sizeof(__nv_bfloat16)
                       + BM * (int)sizeof(float);
        cudaFuncSetAttribute(k_logmap_gemm,
                             cudaFuncAttributeMaxDynamicSharedMemorySize, SMEM);
        const int ntiles = (N + BM - 1) / BM;
        int grid = 296;
        if (grid > ntiles) grid = ntiles;
        k_logmap_gemm<<<grid, 256, SMEM>>>(x, b, N, ntiles);
    }

    // 3. join, then gather
    cudaStreamWaitEvent(0, evB, 0);
    {
        long long threads = (long long)N * 32;
        int grid = (int)((threads + 255) / 256);
        k_gather<<<grid, 256>>>(out, N);
    }
}

// round 17
// speedup vs baseline: 1.4209x; 1.0450x over previous
#include <cuda_runtime.h>
#include <cuda_bf16.h>
#include <cuda_fp16.h>
#include <cstdint>

#define DFEAT 128
#define NMAX  50000
#define NPAD  50176      // 49 * 1024
#define EMAX  600000
#define BM    64
#define LDSK  136        // smem row stride (bf16) -> 272B rows
#define SCANB 49

// scratch (no allocations allowed). Zero-initialized at load; k_gather's
// epilogue restores zeros each run (deterministic, graph-safe).
__device__ __align__(16) __half g_h[NMAX * DFEAT];    // fp16 features (no dinv)
__device__ __align__(16) int   g_cin[NPAD];
__device__ __align__(16) int   g_cout[NPAD];
__device__ __align__(16) float g_dinvf[NPAD];
__device__ __align__(16) int   g_off[NPAD + 1];
__device__ __align__(16) int   g_cur[NPAD];
__device__ __align__(16) int   g_srcs[EMAX];
__device__ __align__(16) unsigned long long g_state[SCANB];
__device__ __align__(16) __nv_bfloat16 g_wh[128 * 128];
__device__ __align__(16) __nv_bfloat16 g_wl[128 * 128];

__device__ __forceinline__ void ldsm_x4(uint32_t addr, uint32_t& r0, uint32_t& r1,
                                        uint32_t& r2, uint32_t& r3) {
    asm volatile("ldmatrix.sync.aligned.m8n8.x4.shared.b16 {%0,%1,%2,%3}, [%4];"
                 : "=r"(r0), "=r"(r1), "=r"(r2), "=r"(r3) : "r"(addr));
}

__device__ __forceinline__ void mma_bf16(float c[4], const uint32_t a[4],
                                         uint32_t b0, uint32_t b1) {
    asm volatile("mma.sync.aligned.m16n8k16.row.col.f32.bf16.bf16.f32 "
                 "{%0,%1,%2,%3},{%4,%5,%6,%7},{%8,%9},{%0,%1,%2,%3};"
                 : "+f"(c[0]), "+f"(c[1]), "+f"(c[2]), "+f"(c[3])
                 : "r"(a[0]), "r"(a[1]), "r"(a[2]), "r"(a[3]), "r"(b0), "r"(b1));
}

__device__ __forceinline__ void cp_async16(uint32_t saddr, const void* gptr) {
    asm volatile("cp.async.ca.shared.global [%0], [%1], 16;"
                 :: "r"(saddr), "l"(gptr) : "memory");
}

// ---------------------------------------------------------------------------
// degree count (counters pre-zeroed by previous run's gather) + W bf16 split
__global__ void k_count(const int* __restrict__ ei, const float* __restrict__ W, int E) {
    int e = blockIdx.x * blockDim.x + threadIdx.x;
    if (e < 128 * 128) {
        float w = W[e];
        __nv_bfloat16 h = __float2bfloat16_rn(w);
        g_wh[e] = h;
        g_wl[e] = __float2bfloat16_rn(w - __bfloat162float(h));
    }
    if (e >= E) return;
    atomicAdd(&g_cout[ei[e]], 1);        // src out-degree
    atomicAdd(&g_cin[ei[E + e]], 1);     // dst in-degree (= CSR count)
}

// ---------------------------------------------------------------------------
// Single-pass exclusive scan (decoupled lookback) + dinvf computation.
__global__ void k_scan(int E) {
    __shared__ int woff[8];
    __shared__ int s_prefix;
    int blk = blockIdx.x, t = threadIdx.x;
    int lane = t & 31, w = t >> 5;
    int base = blk * 1024 + t * 4;
    int4 c = *(const int4*)&g_cin[base];
    // dinvf = rsqrt(max(cin+cout,1)) per node (consumed by gather)
    {
        int4 co = *(const int4*)&g_cout[base];
        float4 dv;
        dv.x = rsqrtf(fmaxf((float)(c.x + co.x), 1.0f));
        dv.y = rsqrtf(fmaxf((float)(c.y + co.y), 1.0f));
        dv.z = rsqrtf(fmaxf((float)(c.z + co.z), 1.0f));
        dv.w = rsqrtf(fmaxf((float)(c.w + co.w), 1.0f));
        *(float4*)&g_dinvf[base] = dv;
    }
    int s = c.x + c.y + c.z + c.w;
    int v = s;
#pragma unroll
    for (int off = 1; off < 32; off <<= 1) {
        int u = __shfl_up_sync(0xFFFFFFFFu, v, off);
        if (lane >= off) v += u;
    }
    if (lane == 31) woff[w] = v;
    __syncthreads();
    if (t == 0) {
        int run = 0;
#pragma unroll
        for (int i = 0; i < 8; i++) { int x = woff[i]; woff[i] = run; run += x; }
        if (blk == 0) {
            atomicExch(&g_state[0], (2ULL << 32) | (unsigned)run);
            s_prefix = 0;
        } else {
            atomicExch(&g_state[blk], (1ULL << 32) | (unsigned)run);
            int exc = 0;
            int p = blk - 1;
            while (p >= 0) {
                unsigned long long st = atomicAdd(&g_state[p], 0ULL);
                unsigned flag = (unsigned)(st >> 32);
                if (flag == 2u) { exc += (int)(st & 0xFFFFFFFFu); break; }
                if (flag == 1u) { exc += (int)(st & 0xFFFFFFFFu); p--; }
            }
            atomicExch(&g_state[blk], (2ULL << 32) | (unsigned)(exc + run));
            s_prefix = exc;
        }
    }
    __syncthreads();
    int run = (v - s) + woff[w] + s_prefix;
    g_off[base]     = run; g_cur[base]     = run; run += c.x;
    g_off[base + 1] = run; g_cur[base + 1] = run; run += c.y;
    g_off[base + 2] = run; g_cur[base + 2] = run; run += c.z;
    g_off[base + 3] = run; g_cur[base + 3] = run;
    if (blk == 0 && t == 0) g_off[NPAD] = E;
}

__global__ void k_fill(const int* __restrict__ ei, int E) {
    int e = blockIdx.x * blockDim.x + threadIdx.x;
    if (e >= E) return;
    int s = ei[e], d = ei[E + e];
    int slot = atomicAdd(&g_cur[d], 1);
    g_srcs[slot] = s;
}

// ---------------------------------------------------------------------------
// Persistent fused GEMM on RAW x; h = scale_r*(x@W^T) + b  (NO dinv — moved
// to gather). Depends only on x, W, b -> launches at t=0, overlaps the build.
__global__ void __launch_bounds__(256, 2)
k_logmap_gemm(const float* __restrict__ x, const float* __restrict__ b,
              int N, int ntiles) {
    extern __shared__ __align__(16) char smraw[];
    __nv_bfloat16* swh = (__nv_bfloat16*)smraw;          // [128][LDSK]
    __nv_bfloat16* swl = swh + 128 * LDSK;
    __nv_bfloat16* sxh = swl + 128 * LDSK;               // [BM][LDSK]
    __nv_bfloat16* sxl = sxh + BM * LDSK;
    float* s_scale = (float*)(sxl + BM * LDSK);          // [BM] logmap scales

    const int tid  = threadIdx.x;
    const int warp = tid >> 5, lane = tid & 31;

    for (int c = tid; c < 2048; c += 256) {
        int row = c >> 4, col8 = (c & 15) * 8;
        uint32_t sh = (uint32_t)__cvta_generic_to_shared(&swh[row * LDSK + col8]);
        cp_async16(sh, &g_wh[row * 128 + col8]);
        uint32_t sl = (uint32_t)__cvta_generic_to_shared(&swl[row * LDSK + col8]);
        cp_async16(sl, &g_wl[row * 128 + col8]);
    }
    asm volatile("cp.async.commit_group;");

    const int wm = warp & 3, wn = warp >> 2;
    const int m0 = wm * 16, n0b = wn * 64;
    const int mat = lane >> 3, mr = lane & 7;
    const int arow = m0 + mr + 8 * (mat & 1);
    const int aoff = 8 * (mat >> 1);
    uint32_t aBaseH = (uint32_t)__cvta_generic_to_shared(&sxh[arow * LDSK + aoff]);
    uint32_t aBaseL = (uint32_t)__cvta_generic_to_shared(&sxl[arow * LDSK + aoff]);
    uint32_t bBaseH[4], bBaseL[4];
#pragma unroll
    for (int g = 0; g < 4; g++) {
        int nrow = n0b + g * 16 + mr + 8 * (mat >> 1);
        int koff = 8 * (mat & 1);
        bBaseH[g] = (uint32_t)__cvta_generic_to_shared(&swh[nrow * LDSK + koff]);
        bBaseL[g] = (uint32_t)__cvta_generic_to_shared(&swl[nrow * LDSK + koff]);
    }

    bool wwait = true;
    const float4* x4 = (const float4*)x;

    for (int tile = blockIdx.x; tile < ntiles; tile += gridDim.x) {
        const int row0 = tile * BM;

        // ---- x-phase: load raw rows, split hi/lo, store (NO reduction) ----
        float4 vbuf[8];
#pragma unroll
        for (int rr = 0; rr < 8; rr++) {
            int r = warp * 8 + rr;
            int row = row0 + r;
            float4 v = (row < N) ? x4[row * 32 + lane] : make_float4(0.f, 0.f, 0.f, 0.f);
            vbuf[rr] = v;
            __nv_bfloat16 h0 = __float2bfloat16_rn(v.x), h1 = __float2bfloat16_rn(v.y);
            __nv_bfloat16 h2 = __float2bfloat16_rn(v.z), h3 = __float2bfloat16_rn(v.w);
            __nv_bfloat16 l0 = __float2bfloat16_rn(v.x - __bfloat162float(h0));
            __nv_bfloat16 l1 = __float2bfloat16_rn(v.y - __bfloat162float(h1));
            __nv_bfloat16 l2 = __float2bfloat16_rn(v.z - __bfloat162float(h2));
            __nv_bfloat16 l3 = __float2bfloat16_rn(v.w - __bfloat162float(h3));
            int kc = lane * 4;
            __nv_bfloat162 hh0; hh0.x = h0; hh0.y = h1;
            __nv_bfloat162 hh1; hh1.x = h2; hh1.y = h3;
            __nv_bfloat162 ll0; ll0.x = l0; ll0.y = l1;
            __nv_bfloat162 ll1; ll1.x = l2; ll1.y = l3;
            *(__nv_bfloat162*)&sxh[r * LDSK + kc]     = hh0;
            *(__nv_bfloat162*)&sxh[r * LDSK + kc + 2] = hh1;
            *(__nv_bfloat162*)&sxl[r * LDSK + kc]     = ll0;
            *(__nv_bfloat162*)&sxl[r * LDSK + kc + 2] = ll1;
        }
        if (wwait) {
            asm volatile("cp.async.wait_group 0;");
            wwait = false;
        }
        __syncthreads();

        // ---- norm/scale: overlapped with MMA, consumed after post-MMA sync
#pragma unroll
        for (int rr = 0; rr < 8; rr++) {
            float4 v = vbuf[rr];
            float s = v.x * v.x + v.y * v.y + v.z * v.z + v.w * v.w;
#pragma unroll
            for (int off = 16; off; off >>= 1) s += __shfl_xor_sync(0xFFFFFFFFu, s, off);
            float norm = sqrtf(s);
            float nc = fminf(fmaxf(norm, 1e-15f), 1.0f - 1e-5f);
            float at = 0.5f * __logf(__fdividef(1.0f + nc, 1.0f - nc));
            float scale = __fdividef(at, fmaxf(norm, 1e-15f));
            if (lane == 0) s_scale[warp * 8 + rr] = scale;
        }

        // ---- MMA mainloop ----
        float acc[8][4];
#pragma unroll
        for (int f = 0; f < 8; f++)
#pragma unroll
            for (int j = 0; j < 4; j++) acc[f][j] = 0.f;

        uint32_t ah[2][4], al[2][4];
        uint32_t bh[2][4], bl[2][4];

        ldsm_x4(aBaseH, ah[0][0], ah[0][1], ah[0][2], ah[0][3]);
        ldsm_x4(aBaseL, al[0][0], al[0][1], al[0][2], al[0][3]);

#pragma unroll
        for (int kk = 0; kk < 8; kk++) {
            const uint32_t kb = kk * 32;
            const int cur = kk & 1, nxt = cur ^ 1;
            ldsm_x4(bBaseH[0] + kb, bh[0][0], bh[0][1], bh[0][2], bh[0][3]);
            ldsm_x4(bBaseL[0] + kb, bl[0][0], bl[0][1], bl[0][2], bl[0][3]);
            if (kk < 7) {
                ldsm_x4(aBaseH + kb + 32, ah[nxt][0], ah[nxt][1], ah[nxt][2], ah[nxt][3]);
                ldsm_x4(aBaseL + kb + 32, al[nxt][0], al[nxt][1], al[nxt][2], al[nxt][3]);
            }
#pragma unroll
            for (int g = 0; g < 4; g++) {
                const int gb = g & 1, gn = gb ^ 1;
                if (g < 3) {
                    ldsm_x4(bBaseH[g + 1] + kb, bh[gn][0], bh[gn][1], bh[gn][2], bh[gn][3]);
                    ldsm_x4(bBaseL[g + 1] + kb, bl[gn][0], bl[gn][1], bl[gn][2], bl[gn][3]);
                }
#pragma unroll
                for (int o = 0; o < 2; o++) {
                    const int f = 2 * g + o;
                    uint32_t b0h = bh[gb][2 * o], b1h = bh[gb][2 * o + 1];
                    uint32_t b0l = bl[gb][2 * o], b1l = bl[gb][2 * o + 1];
                    mma_bf16(acc[f], ah[cur], b0h, b1h);   // hh
                    mma_bf16(acc[f], ah[cur], b0l, b1l);   // hl
                    mma_bf16(acc[f], al[cur], b0h, b1h);   // lh (ll dropped)
                }
            }
        }
        __syncthreads();   // MMA + s_scale writes complete

        // ---- epilogue: *scale_r, +bias, fp16 store (no dinv) ----
        int lr0 = m0 + (lane >> 2);
        int lr1 = lr0 + 8;
        int r0r = row0 + lr0;
        int r1r = r0r + 8;
        float sc0 = s_scale[lr0], sc1 = s_scale[lr1];
        __half2* hp = (__half2*)g_h;
#pragma unroll
        for (int f = 0; f < 8; f++) {
            int c = n0b + f * 8 + 2 * (lane & 3);
            float bx = b[c], by = b[c + 1];
            if (r0r < N)
                hp[(r0r * DFEAT + c) >> 1] =
                    __floats2half2_rn(acc[f][0] * sc0 + bx, acc[f][1] * sc0 + by);
            if (r1r < N)
                hp[(r1r * DFEAT + c) >> 1] =
                    __floats2half2_rn(acc[f][2] * sc1 + bx, acc[f][3] * sc1 + by);
        }
        __syncthreads();   // epilogue read of s_scale done; safe to refill
    }
}

// ---------------------------------------------------------------------------
// CSR gather: sum dinvf[src]*h[src], * dinvf[dst], expmap0.
__global__ void k_gather(float* __restrict__ out, int N) {
    int t = blockIdx.x * blockDim.x + threadIdx.x;
    if (t < SCANB) g_state[t] = 0ULL;
    int gw = t >> 5;
    int lane = threadIdx.x & 31;
    if (gw >= N) return;
    int beg = g_off[gw], end = g_off[gw + 1];
    const uint2* hh = (const uint2*)g_h;     // 32 uint2 per row

    float4 a0 = make_float4(0.f, 0.f, 0.f, 0.f);
    float4 a1 = make_float4(0.f, 0.f, 0.f, 0.f);
    int p = beg;
    for (; p + 4 <= end; p += 4) {
        int s0 = __ldg(&g_srcs[p]);
        int s1 = __ldg(&g_srcs[p + 1]);
        int s2 = __ldg(&g_srcs[p + 2]);
        int s3 = __ldg(&g_srcs[p + 3]);
        float c0 = __ldg(&g_dinvf[s0]);
        float c1 = __ldg(&g_dinvf[s1]);
        float c2 = __ldg(&g_dinvf[s2]);
        float c3 = __ldg(&g_dinvf[s3]);
        uint2 u0 = hh[s0 * 32 + lane];
        uint2 u1 = hh[s1 * 32 + lane];
        uint2 u2 = hh[s2 * 32 + lane];
        uint2 u3 = hh[s3 * 32 + lane];
        float2 f;
        f = __half22float2(*(__half2*)&u0.x); a0.x = fmaf(f.x, c0, a0.x); a0.y = fmaf(f.y, c0, a0.y);
        f = __half22float2(*(__half2*)&u0.y); a0.z = fmaf(f.x, c0, a0.z); a0.w = fmaf(f.y, c0, a0.w);
        f = __half22float2(*(__half2*)&u1.x); a1.x = fmaf(f.x, c1, a1.x); a1.y = fmaf(f.y, c1, a1.y);
        f = __half22float2(*(__half2*)&u1.y); a1.z = fmaf(f.x, c1, a1.z); a1.w = fmaf(f.y, c1, a1.w);
        f = __half22float2(*(__half2*)&u2.x); a0.x = fmaf(f.x, c2, a0.x); a0.y = fmaf(f.y, c2, a0.y);
        f = __half22float2(*(__half2*)&u2.y); a0.z = fmaf(f.x, c2, a0.z); a0.w = fmaf(f.y, c2, a0.w);
        f = __half22float2(*(__half2*)&u3.x); a1.x = fmaf(f.x, c3, a1.x); a1.y = fmaf(f.y, c3, a1.y);
        f = __half22float2(*(__half2*)&u3.y); a1.z = fmaf(f.x, c3, a1.z); a1.w = fmaf(f.y, c3, a1.w);
    }
    for (; p < end; p++) {
        int s0 = __ldg(&g_srcs[p]);
        float c0 = __ldg(&g_dinvf[s0]);
        uint2 u0 = hh[s0 * 32 + lane];
        float2 f;
        f = __half22float2(*(__half2*)&u0.x); a0.x = fmaf(f.x, c0, a0.x); a0.y = fmaf(f.y, c0, a0.y);
        f = __half22float2(*(__half2*)&u0.y); a0.z = fmaf(f.x, c0, a0.z); a0.w = fmaf(f.y, c0, a0.w);
    }
    float di = g_dinvf[gw];
    if (lane == 0) { g_cin[gw] = 0; g_cout[gw] = 0; }   // reset for next run
    float4 acc;
    acc.x = (a0.x + a1.x) * di;
    acc.y = (a0.y + a1.y) * di;
    acc.z = (a0.z + a1.z) * di;
    acc.w = (a0.w + a1.w) * di;

    float s = acc.x * acc.x + acc.y * acc.y + acc.z * acc.z + acc.w * acc.w;
#pragma unroll
    for (int off = 16; off; off >>= 1) s += __shfl_xor_sync(0xFFFFFFFFu, s, off);
    float norm = sqrtf(s);
    float e2 = __expf(2.0f * norm);
    float scale = __fdividef(e2 - 1.0f, (e2 + 1.0f) * fmaxf(norm, 1e-15f));
    acc.x *= scale; acc.y *= scale; acc.z *= scale; acc.w *= scale;
    ((float4*)out)[gw * 32 + lane] = acc;
}

// ---------------------------------------------------------------------------
extern "C" void kernel_launch(void* const* d_in, const int* in_sizes, int n_in,
                              void* d_out, int out_size) {
    const float* x  = (const float*)d_in[0];
    const int*   ei = (const int*)d_in[1];
    const float* W  = (const float*)d_in[2];
    const float* b  = (const float*)d_in[3];
    float* out = (float*)d_out;

    const int N = in_sizes[0] / DFEAT;
    const int E = in_sizes[1] / 2;

    // lazy-created side stream + fork/join events (host objects; no device mem)
    static cudaStream_t sB = nullptr;
    static cudaEvent_t evFork = nullptr, evB = nullptr;
    if (sB == nullptr) {
        cudaStreamCreateWithFlags(&sB, cudaStreamNonBlocking);
        cudaEventCreateWithFlags(&evFork, cudaEventDisableTiming);
        cudaEventCreateWithFlags(&evB, cudaEventDisableTiming);
    }

    // FORK: event recorded on the (possibly capturing) origin stream; sB joins
    // the capture by waiting on it. Only then may sB receive work.
    cudaEventRecord(evFork, 0);
    cudaStreamWaitEvent(sB, evFork, 0);

    // branch B (side stream): full graph build — count -> scan(+dinvf) -> fill
    k_count<<<(E + 255) / 256, 256, 0, sB>>>(ei, W, E);
    k_scan<<<SCANB, 256, 0, sB>>>(E);
    k_fill<<<(E + 255) / 256, 256, 0, sB>>>(ei, E);
    cudaEventRecord(evB, sB);

    // branch A (main stream): GEMM — depends only on x, W, b; starts at t=0
    {
        const int SMEM = (2 * 128 * LDSK + 2 * BM * LDSK) * (int)sizeof(__nv_bfloat16)
                       + BM * (int)sizeof(float);
        cudaFuncSetAttribute(k_logmap_gemm,
                             cudaFuncAttributeMaxDynamicSharedMemorySize, SMEM);
        const int ntiles = (N + BM - 1) / BM;
        int grid = 296;
        if (grid > ntiles) grid = ntiles;
        k_logmap_gemm<<<grid, 256, SMEM>>>(x, b, N, ntiles);
    }

    // JOIN: origin stream waits for the build branch, then gather
    cudaStreamWaitEvent(0, evB, 0);
    {
        long long threads = (long long)N * 32;
        int grid = (int)((threads + 255) / 256);
        k_gather<<<grid, 256>>>(out, N);
    }
}